// round 7
// baseline (speedup 1.0000x reference)
#include <cuda_runtime.h>
#include <cuda_bf16.h>
#include <math.h>
#include <stdint.h>

// ---------------- problem constants ----------------
#define BB    2
#define LL    8192
#define N2    16384      // 2*L, FFT length = 4^7
#define DD    768
#define FF    768
#define ORDER 2
#define INNER 2304       // F*(ORDER+1)
#define NPAIR 384        // FF/2 channel pairs
#define FNTH  1024       // threads for FFT kernels
#define SMEM_FFT ((N2 + N2/4) * 8)   // 16384 float2 data + 4096 float2 twiddles = 163840 B

// GEMM smem: 4 split tiles of 32 x 136 uint32
#define GPAD  136
#define GTILE (32 * GPAD)
#define SMEM_GEMM (4 * GTILE * 4)    // 69632 B

// ---------------- scratch (static device memory; no allocation) ----------------
__device__ float2 d_h2 [(size_t)ORDER * NPAIR * N2];        // filter pairs: .x = ch 2i, .y = ch 2i+1
__device__ float2 d_hf [(size_t)ORDER * NPAIR * 2 * N2];    // spectra [o][pair][ch][p] dr4 order, /n
__device__ float  d_proj[(size_t)BB * INNER * LL];          // in-proj output, [b][c][l]
__device__ float  d_vout[(size_t)BB * FF * LL];             // final v, [b][f][l]

// ---------------- complex helpers ----------------
__device__ __forceinline__ float2 cadd(float2 a, float2 b) { return make_float2(a.x + b.x, a.y + b.y); }
__device__ __forceinline__ float2 csub(float2 a, float2 b) { return make_float2(a.x - b.x, a.y - b.y); }
__device__ __forceinline__ float2 cmul(float2 a, float2 b) {
    return make_float2(a.x * b.x - a.y * b.y, a.x * b.y + a.y * b.x);
}
__device__ __forceinline__ float2 cmulc(float2 a, float2 b) {   // a * conj(b)
    return make_float2(a.x * b.x + a.y * b.y, a.y * b.x - a.x * b.y);
}

// base-4 digit reversal of a 14-bit index (involution)
__device__ __forceinline__ int dr4(int p) {
    unsigned r = __brev((unsigned)p) >> 18;
    return (int)(((r & 0x2AAAu) >> 1) | ((r & 0x1555u) << 1));
}

// ---------------- radix-4 FFT (in-place, smem, 7 stages) ----------------
__device__ __forceinline__ void fft4_fwd(float2* data, const float2* tw4, int tid) {
    #pragma unroll
    for (int t = 0; t < 7; t++) {
        const int lq = 12 - 2 * t;
        const int Q  = 1 << lq;
        #pragma unroll
        for (int u0 = 0; u0 < N2 / 4 / FNTH; u0++) {
            int u = tid + u0 * FNTH;
            int j = u & (Q - 1);
            int base = ((u >> lq) << (lq + 2)) + j;
            float2 a = data[base], b = data[base + Q];
            float2 c = data[base + 2 * Q], d = data[base + 3 * Q];
            float2 t0 = cadd(a, c), t1 = csub(a, c);
            float2 t2 = cadd(b, d), t3 = csub(b, d);
            float2 w1 = tw4[j << (2 * t)];
            float2 w2 = cmul(w1, w1);
            float2 w3 = cmul(w2, w1);
            data[base] = cadd(t0, t2);
            float2 X1 = make_float2(t1.x + t3.y, t1.y - t3.x);
            float2 X2 = csub(t0, t2);
            float2 X3 = make_float2(t1.x - t3.y, t1.y + t3.x);
            data[base + Q]     = cmul(X1, w1);
            data[base + 2 * Q] = cmul(X2, w2);
            data[base + 3 * Q] = cmul(X3, w3);
        }
        __syncthreads();
    }
}

__device__ __forceinline__ void fft4_inv(float2* data, const float2* tw4, int tid) {
    #pragma unroll
    for (int t = 0; t < 7; t++) {
        const int lq = 2 * t;
        const int Q  = 1 << lq;
        #pragma unroll
        for (int u0 = 0; u0 < N2 / 4 / FNTH; u0++) {
            int u = tid + u0 * FNTH;
            int j = u & (Q - 1);
            int base = ((u >> lq) << (lq + 2)) + j;
            float2 w1 = tw4[j << (12 - 2 * t)];
            float2 w2 = cmul(w1, w1);
            float2 w3 = cmul(w2, w1);
            float2 b0 = data[base];
            float2 b1 = cmulc(data[base + Q],     w1);
            float2 b2 = cmulc(data[base + 2 * Q], w2);
            float2 b3 = cmulc(data[base + 3 * Q], w3);
            float2 s0 = cadd(b0, b2), s1 = csub(b0, b2);
            float2 s2 = cadd(b1, b3), s3 = csub(b1, b3);
            data[base]         = cadd(s0, s2);
            data[base + Q]     = make_float2(s1.x - s3.y, s1.y + s3.x);
            data[base + 2 * Q] = csub(s0, s2);
            data[base + 3 * Q] = make_float2(s1.x + s3.y, s1.y - s3.x);
        }
        __syncthreads();
    }
}

__device__ __forceinline__ void build_twiddles4(float2* tw4, int tid) {
    #pragma unroll
    for (int i = 0; i < N2 / 4 / FNTH; i++) {
        int j = tid + i * FNTH;
        float x = -(float)j * (1.0f / 8192.0f);
        float s, c;
        sincospif(x, &s, &c);
        tw4[j] = make_float2(c, s);
    }
}

__device__ __forceinline__ float scval(const float* __restrict__ row, int l,
                                       float w0, float w1, float w2, float bb) {
    float acc = bb + w1 * row[l];
    if (l > 0)      acc += w0 * row[l - 1];
    if (l < LL - 1) acc += w2 * row[l + 1];
    return acc;
}

// ---------------- tf32x3 MMA helpers ----------------
__device__ __forceinline__ void split_tf32(float x, uint32_t& hi, uint32_t& lo) {
    uint32_t xb = __float_as_uint(x);
    hi = xb & 0xFFFFE000u;
    float lof = x - __uint_as_float(hi);
    lo = __float_as_uint(lof) & 0xFFFFE000u;
}

__device__ __forceinline__ void mma_tf32(float* c, const uint32_t* a, const uint32_t* b) {
    asm volatile(
        "mma.sync.aligned.m16n8k8.row.col.f32.tf32.tf32.f32 "
        "{%0,%1,%2,%3}, {%4,%5,%6,%7}, {%8,%9}, {%0,%1,%2,%3};"
        : "+f"(c[0]), "+f"(c[1]), "+f"(c[2]), "+f"(c[3])
        : "r"(a[0]), "r"(a[1]), "r"(a[2]), "r"(a[3]), "r"(b[0]), "r"(b[1]));
}

// ---------------- kernel 1: filter MLP + modulation (pair-interleaved output) ----
__global__ __launch_bounds__(256) void hfilter_kernel(
    const float* __restrict__ w1, const float* __restrict__ b1,
    const float* __restrict__ w2, const float* __restrict__ b2,
    const float* __restrict__ decay)
{
    __shared__ float hid[16][64];
    const int p0  = blockIdx.x * 16;
    const int tid = threadIdx.x;

    for (int idx = tid; idx < 16 * 64; idx += 256) {
        int pp = idx >> 6;
        int u  = idx & 63;
        int p  = p0 + pp;
        float off = (p < LL) ? (float)p : (float)(p - N2);
        float t[9];
        t[0] = off * (1.0f / 8192.0f);
        const float step = (8192.0f - 4.0f) / 3.0f;
        #pragma unroll
        for (int i = 0; i < 4; i++) {
            float period = 4.0f + step * (float)i;
            float fr = 6.28318530717958647692f / period;
            float ph = off * fr;
            t[1 + i] = cosf(ph);
            t[5 + i] = sinf(ph);
        }
        float a = b1[u];
        #pragma unroll
        for (int k = 0; k < 9; k++) a += t[k] * w1[k * 64 + u];
        hid[pp][u] = sinf(a);
    }
    __syncthreads();

    for (int oc = tid; oc < ORDER * FF; oc += 256) {
        float acc[16];
        float bv = b2[oc];
        #pragma unroll
        for (int pp = 0; pp < 16; pp++) acc[pp] = bv;
        for (int k = 0; k < 64; k++) {
            float wv = w2[k * (ORDER * FF) + oc];
            #pragma unroll
            for (int pp = 0; pp < 16; pp++) acc[pp] += hid[pp][k] * wv;
        }
        float dec = fabsf(decay[oc]);
        int o = oc / FF, f = oc - o * FF;
        float* dst = (float*)(d_h2 + ((size_t)(o * NPAIR + (f >> 1))) * N2 + p0) + (f & 1);
        #pragma unroll
        for (int pp = 0; pp < 16; pp++) {
            int p = p0 + pp;
            float mod = (p < LL) ? (float)p * (1.0f / 8191.0f)
                                 : (float)(N2 - 1 - p) * (1.0f / 8191.0f);
            dst[2 * pp] = acc[pp] * expf(-mod * dec);
        }
    }
}

// ---------------- kernel 2: paired filter FFT (radix-4) ----------------
__global__ __launch_bounds__(FNTH) void hfft_kernel() {
    extern __shared__ float2 smem_f2[];
    float2* data = smem_f2;
    float2* tw4  = smem_f2 + N2;
    const int cp  = blockIdx.x;
    const int tid = threadIdx.x;

    build_twiddles4(tw4, tid);
    const float2* src = d_h2 + (size_t)cp * N2;
    #pragma unroll
    for (int i = 0; i < N2 / FNTH; i++) {
        int idx = tid + i * FNTH;
        data[idx] = src[idx];
    }
    __syncthreads();
    fft4_fwd(data, tw4, tid);

    const float s = 0.5f / (float)N2;
    float2* hf0 = d_hf + (size_t)(cp * 2 + 0) * N2;
    float2* hf1 = d_hf + (size_t)(cp * 2 + 1) * N2;
    #pragma unroll
    for (int i = 0; i < N2 / FNTH; i++) {
        int p  = tid + i * FNTH;
        int k  = dr4(p);
        int km = (N2 - k) & (N2 - 1);
        int pm = dr4(km);
        if (p <= pm) {
            float2 z1 = data[p];
            float2 z2 = data[pm];
            float2 H0 = make_float2(s * (z1.x + z2.x),  s * (z1.y - z2.y));
            float2 H1 = make_float2(s * (z1.y + z2.y), -s * (z1.x - z2.x));
            hf0[p]  = H0;
            hf1[p]  = H1;
            hf0[pm] = make_float2(H0.x, -H0.y);
            hf1[pm] = make_float2(H1.x, -H1.y);
        }
    }
}

// ---------------- kernel 3: in-projection GEMM, tf32x3, precomputed split tiles ----
// C[b,c,l] = sum_d U[b,l,d]*W[d,c] + bias[c]  (output transposed [c][l])
__global__ __launch_bounds__(256) void gemm_inproj_tc(
    const float* __restrict__ U, const float* __restrict__ W,
    const float* __restrict__ bias)
{
    extern __shared__ uint32_t smU[];
    uint32_t* Ah = smU;
    uint32_t* Al = Ah + GTILE;
    uint32_t* Bh = Al + GTILE;
    uint32_t* Bl = Bh + GTILE;

    const int b  = blockIdx.z;
    const int c0 = blockIdx.x * 128;
    const int l0 = blockIdx.y * 128;
    const float* Ub = U + (size_t)b * LL * DD;
    float* Cb = d_proj + (size_t)b * INNER * LL;

    const int tid    = threadIdx.x;
    const int wid    = tid >> 5;
    const int lane   = tid & 31;
    const int warp_m = wid >> 2;    // 0..1
    const int warp_n = wid & 3;     // 0..3
    const int q      = lane >> 2;   // 0..7
    const int r      = lane & 3;    // 0..3

    float acc[4][4][4];
    #pragma unroll
    for (int mt = 0; mt < 4; mt++)
        #pragma unroll
        for (int nt = 0; nt < 4; nt++)
            #pragma unroll
            for (int j = 0; j < 4; j++) acc[mt][nt][j] = 0.0f;

    for (int k0 = 0; k0 < DD; k0 += 32) {
        #pragma unroll
        for (int i = 0; i < 4; i++) {
            int slot = tid + i * 256;
            // A: row-major [l][d] — float4 along k, split + scatter to 4 rows
            int m  = slot >> 3;
            int kq = (slot & 7) * 4;
            float4 v = *(const float4*)(Ub + (size_t)(l0 + m) * DD + k0 + kq);
            uint32_t h, lo;
            split_tf32(v.x, h, lo); Ah[(kq + 0) * GPAD + m] = h; Al[(kq + 0) * GPAD + m] = lo;
            split_tf32(v.y, h, lo); Ah[(kq + 1) * GPAD + m] = h; Al[(kq + 1) * GPAD + m] = lo;
            split_tf32(v.z, h, lo); Ah[(kq + 2) * GPAD + m] = h; Al[(kq + 2) * GPAD + m] = lo;
            split_tf32(v.w, h, lo); Ah[(kq + 3) * GPAD + m] = h; Al[(kq + 3) * GPAD + m] = lo;
            // B: row-major [d][c] — float4 along n, split + vector store
            int nq = (slot & 31) * 4;
            int kk = slot >> 5;
            float4 w4 = *(const float4*)(W + (size_t)(k0 + kk) * INNER + c0 + nq);
            uint4 wh, wl;
            split_tf32(w4.x, wh.x, wl.x);
            split_tf32(w4.y, wh.y, wl.y);
            split_tf32(w4.z, wh.z, wl.z);
            split_tf32(w4.w, wh.w, wl.w);
            *(uint4*)&Bh[kk * GPAD + nq] = wh;
            *(uint4*)&Bl[kk * GPAD + nq] = wl;
        }
        __syncthreads();

        #pragma unroll
        for (int s = 0; s < 4; s++) {
            const int kb = s * 8;
            const int r0o = (kb + r) * GPAD;
            const int r1o = (kb + 4 + r) * GPAD;
            uint32_t bh[4][2], bl[4][2];
            #pragma unroll
            for (int nt = 0; nt < 4; nt++) {
                int n = warp_n * 32 + nt * 8 + q;
                bh[nt][0] = Bh[r0o + n]; bh[nt][1] = Bh[r1o + n];
                bl[nt][0] = Bl[r0o + n]; bl[nt][1] = Bl[r1o + n];
            }
            #pragma unroll
            for (int mt = 0; mt < 4; mt++) {
                int m = warp_m * 64 + mt * 16 + q;
                uint32_t ah[4], al[4];
                ah[0] = Ah[r0o + m]; ah[1] = Ah[r0o + m + 8];
                ah[2] = Ah[r1o + m]; ah[3] = Ah[r1o + m + 8];
                al[0] = Al[r0o + m]; al[1] = Al[r0o + m + 8];
                al[2] = Al[r1o + m]; al[3] = Al[r1o + m + 8];
                #pragma unroll
                for (int nt = 0; nt < 4; nt++) {
                    mma_tf32(acc[mt][nt], ah, bh[nt]);
                    mma_tf32(acc[mt][nt], ah, bl[nt]);
                    mma_tf32(acc[mt][nt], al, bh[nt]);
                }
            }
        }
        __syncthreads();
    }

    // epilogue: transpose through smem, store [c][l] rows contiguous
    float* st = (float*)smU;   // 32 x 129 floats scratch
    for (int p = 0; p < 4; p++) {
        if (warp_n == p) {
            #pragma unroll
            for (int mt = 0; mt < 4; mt++)
                #pragma unroll
                for (int nt = 0; nt < 4; nt++) {
                    int m = warp_m * 64 + mt * 16 + q;
                    int n = nt * 8 + 2 * r;
                    st[(n    ) * 129 + m    ] = acc[mt][nt][0];
                    st[(n + 1) * 129 + m    ] = acc[mt][nt][1];
                    st[(n    ) * 129 + m + 8] = acc[mt][nt][2];
                    st[(n + 1) * 129 + m + 8] = acc[mt][nt][3];
                }
        }
        __syncthreads();
        int row = tid >> 3;      // 0..31
        int cq  = tid & 7;       // 0..7
        int c   = c0 + p * 32 + row;
        float bb = bias[c];
        float* dst = Cb + (size_t)c * LL + l0;
        #pragma unroll
        for (int ii = 0; ii < 4; ii++) {
            int mq = cq + 8 * ii;
            float4 v = make_float4(st[row * 129 + mq * 4 + 0] + bb,
                                   st[row * 129 + mq * 4 + 1] + bb,
                                   st[row * 129 + mq * 4 + 2] + bb,
                                   st[row * 129 + mq * 4 + 3] + bb);
            *(float4*)(dst + mq * 4) = v;
        }
        __syncthreads();
    }
}

// ---------------- kernel 4: fused FFT conv (radix-4, 2 channels/block) ----------------
__global__ __launch_bounds__(FNTH) void fftconv_kernel(
    const float* __restrict__ bias,
    const float* __restrict__ sw, const float* __restrict__ sb)
{
    extern __shared__ float2 smem_f2[];
    float2* data = smem_f2;
    float2* tw4  = smem_f2 + N2;
    const int pr  = blockIdx.x;
    const int b   = blockIdx.y;
    const int tid = threadIdx.x;
    const int f0  = 2 * pr;
    const int f1  = 2 * pr + 1;

    build_twiddles4(tw4, tid);

    float v0[LL / FNTH], v1[LL / FNTH];
    {
        const float* r0 = d_proj + ((size_t)b * INNER + f0) * LL;
        const float* r1 = d_proj + ((size_t)b * INNER + f1) * LL;
        float a0 = sw[f0], a1 = sw[INNER + f0], a2 = sw[2 * INNER + f0], ab = sb[f0];
        float c0 = sw[f1], c1 = sw[INNER + f1], c2 = sw[2 * INNER + f1], cb = sb[f1];
        #pragma unroll
        for (int i = 0; i < LL / FNTH; i++) {
            int l = tid + i * FNTH;
            v0[i] = scval(r0, l, a0, a1, a2, ab);
            v1[i] = scval(r1, l, c0, c1, c2, cb);
        }
    }

    #pragma unroll 1
    for (int o = 0; o < ORDER; o++) {
        #pragma unroll
        for (int i = 0; i < LL / FNTH; i++)
            data[tid + i * FNTH] = make_float2(v0[i], v1[i]);
        #pragma unroll
        for (int i = LL / FNTH; i < N2 / FNTH; i++)
            data[tid + i * FNTH] = make_float2(0.0f, 0.0f);
        __syncthreads();

        fft4_fwd(data, tw4, tid);

        const float2* hf0 = d_hf + (size_t)((o * NPAIR + pr) * 2 + 0) * N2;
        const float2* hf1 = d_hf + (size_t)((o * NPAIR + pr) * 2 + 1) * N2;
        #pragma unroll
        for (int i = 0; i < N2 / FNTH; i++) {
            int p  = tid + i * FNTH;
            int k  = dr4(p);
            int km = (N2 - k) & (N2 - 1);
            int pm = dr4(km);
            if (p <= pm) {
                float2 z1 = data[p];
                float2 z2 = data[pm];
                float2 V0 = make_float2(0.5f * (z1.x + z2.x),  0.5f * (z1.y - z2.y));
                float2 V1 = make_float2(0.5f * (z1.y + z2.y), -0.5f * (z1.x - z2.x));
                float2 H0 = hf0[p];
                float2 H1 = hf1[p];
                float2 Y0 = cmul(V0, H0);
                float2 Y1 = cmul(V1, H1);
                data[p]  = make_float2(Y0.x - Y1.y, Y0.y + Y1.x);
                data[pm] = make_float2(Y0.x + Y1.y, Y1.x - Y0.y);
            }
        }
        __syncthreads();

        fft4_inv(data, tw4, tid);

        float bs0 = bias[o * FF + f0];
        float bs1 = bias[o * FF + f1];
        const int g0c = (1 + o) * FF + f0;
        const int g1c = (1 + o) * FF + f1;
        const float* g0r = d_proj + ((size_t)b * INNER + g0c) * LL;
        const float* g1r = d_proj + ((size_t)b * INNER + g1c) * LL;
        float ga0 = sw[g0c], ga1 = sw[INNER + g0c], ga2 = sw[2 * INNER + g0c], gab = sb[g0c];
        float gc0 = sw[g1c], gc1 = sw[INNER + g1c], gc2 = sw[2 * INNER + g1c], gcb = sb[g1c];
        #pragma unroll
        for (int i = 0; i < LL / FNTH; i++) {
            int l = tid + i * FNTH;
            float2 y = data[l];
            float g0 = scval(g0r, l, ga0, ga1, ga2, gab);
            float g1 = scval(g1r, l, gc0, gc1, gc2, gcb);
            v0[i] = (y.x + v0[i] * bs0) * g0;
            v1[i] = (y.y + v1[i] * bs1) * g1;
        }
        __syncthreads();
    }
    float* dst0 = d_vout + ((size_t)b * FF + f0) * LL;
    float* dst1 = d_vout + ((size_t)b * FF + f1) * LL;
    #pragma unroll
    for (int i = 0; i < LL / FNTH; i++) {
        dst0[tid + i * FNTH] = v0[i];
        dst1[tid + i * FNTH] = v1[i];
    }
}

// ---------------- kernel 5: output GEMM, tf32x3, precomputed split tiles ----------
// Y[b,l,d] = sum_f V[b][f][l]*W[f,d] + bias[d]
__global__ __launch_bounds__(256) void gemm_out_tc(
    const float* __restrict__ W, const float* __restrict__ bias,
    float* __restrict__ Y)
{
    extern __shared__ uint32_t smU[];
    uint32_t* Ah = smU;
    uint32_t* Al = Ah + GTILE;
    uint32_t* Bh = Al + GTILE;
    uint32_t* Bl = Bh + GTILE;

    const int b  = blockIdx.z;
    const int d0 = blockIdx.x * 128;
    const int l0 = blockIdx.y * 128;
    const float* Vb = d_vout + (size_t)b * FF * LL;
    float* Yb = Y + (size_t)b * LL * DD;

    const int tid    = threadIdx.x;
    const int wid    = tid >> 5;
    const int lane   = tid & 31;
    const int warp_m = wid >> 2;
    const int warp_n = wid & 3;
    const int q      = lane >> 2;
    const int r      = lane & 3;

    float acc[4][4][4];
    #pragma unroll
    for (int mt = 0; mt < 4; mt++)
        #pragma unroll
        for (int nt = 0; nt < 4; nt++)
            #pragma unroll
            for (int j = 0; j < 4; j++) acc[mt][nt][j] = 0.0f;

    for (int k0 = 0; k0 < FF; k0 += 32) {
        #pragma unroll
        for (int i = 0; i < 4; i++) {
            int slot = tid + i * 256;
            int mq = (slot & 31) * 4;
            int kk = slot >> 5;
            // A: column-major source [f][l] — float4 along m
            float4 v = *(const float4*)(Vb + (size_t)(k0 + kk) * LL + l0 + mq);
            uint4 vh, vl;
            split_tf32(v.x, vh.x, vl.x);
            split_tf32(v.y, vh.y, vl.y);
            split_tf32(v.z, vh.z, vl.z);
            split_tf32(v.w, vh.w, vl.w);
            *(uint4*)&Ah[kk * GPAD + mq] = vh;
            *(uint4*)&Al[kk * GPAD + mq] = vl;
            // B: row-major [f][d] — float4 along n
            float4 w4 = *(const float4*)(W + (size_t)(k0 + kk) * DD + d0 + mq);
            uint4 wh, wl;
            split_tf32(w4.x, wh.x, wl.x);
            split_tf32(w4.y, wh.y, wl.y);
            split_tf32(w4.z, wh.z, wl.z);
            split_tf32(w4.w, wh.w, wl.w);
            *(uint4*)&Bh[kk * GPAD + mq] = wh;
            *(uint4*)&Bl[kk * GPAD + mq] = wl;
        }
        __syncthreads();

        #pragma unroll
        for (int s = 0; s < 4; s++) {
            const int kb = s * 8;
            const int r0o = (kb + r) * GPAD;
            const int r1o = (kb + 4 + r) * GPAD;
            uint32_t bh[4][2], bl[4][2];
            #pragma unroll
            for (int nt = 0; nt < 4; nt++) {
                int n = warp_n * 32 + nt * 8 + q;
                bh[nt][0] = Bh[r0o + n]; bh[nt][1] = Bh[r1o + n];
                bl[nt][0] = Bl[r0o + n]; bl[nt][1] = Bl[r1o + n];
            }
            #pragma unroll
            for (int mt = 0; mt < 4; mt++) {
                int m = warp_m * 64 + mt * 16 + q;
                uint32_t ah[4], al[4];
                ah[0] = Ah[r0o + m]; ah[1] = Ah[r0o + m + 8];
                ah[2] = Ah[r1o + m]; ah[3] = Ah[r1o + m + 8];
                al[0] = Al[r0o + m]; al[1] = Al[r0o + m + 8];
                al[2] = Al[r1o + m]; al[3] = Al[r1o + m + 8];
                #pragma unroll
                for (int nt = 0; nt < 4; nt++) {
                    mma_tf32(acc[mt][nt], ah, bh[nt]);
                    mma_tf32(acc[mt][nt], ah, bl[nt]);
                    mma_tf32(acc[mt][nt], al, bh[nt]);
                }
            }
        }
        __syncthreads();
    }

    #pragma unroll
    for (int mt = 0; mt < 4; mt++) {
        #pragma unroll
        for (int nt = 0; nt < 4; nt++) {
            int n = d0 + warp_n * 32 + nt * 8 + 2 * r;
            float b0v = bias[n], b1v = bias[n + 1];
            int m = l0 + warp_m * 64 + mt * 16 + q;
            float2 o0 = make_float2(acc[mt][nt][0] + b0v, acc[mt][nt][1] + b1v);
            float2 o1 = make_float2(acc[mt][nt][2] + b0v, acc[mt][nt][3] + b1v);
            *(float2*)(Yb + (size_t)m * DD + n)       = o0;
            *(float2*)(Yb + (size_t)(m + 8) * DD + n) = o1;
        }
    }
}

// ---------------- launch ----------------
extern "C" void kernel_launch(void* const* d_in, const int* in_sizes, int n_in,
                              void* d_out, int out_size) {
    const float* u     = (const float*)d_in[0];
    const float* fw1   = (const float*)d_in[1];
    const float* fb1   = (const float*)d_in[2];
    const float* fw2   = (const float*)d_in[3];
    const float* fb2   = (const float*)d_in[4];
    const float* decay = (const float*)d_in[5];
    const float* bias  = (const float*)d_in[6];
    const float* ipw   = (const float*)d_in[7];
    const float* ipb   = (const float*)d_in[8];
    const float* sw    = (const float*)d_in[9];
    const float* sb    = (const float*)d_in[10];
    const float* ow    = (const float*)d_in[11];
    const float* ob    = (const float*)d_in[12];
    float* y = (float*)d_out;

    cudaFuncSetAttribute(hfft_kernel,     cudaFuncAttributeMaxDynamicSharedMemorySize, SMEM_FFT);
    cudaFuncSetAttribute(fftconv_kernel,  cudaFuncAttributeMaxDynamicSharedMemorySize, SMEM_FFT);
    cudaFuncSetAttribute(gemm_inproj_tc,  cudaFuncAttributeMaxDynamicSharedMemorySize, SMEM_GEMM);
    cudaFuncSetAttribute(gemm_out_tc,     cudaFuncAttributeMaxDynamicSharedMemorySize, SMEM_GEMM);

    hfilter_kernel<<<N2 / 16, 256>>>(fw1, fb1, fw2, fb2, decay);
    hfft_kernel<<<ORDER * NPAIR, FNTH, SMEM_FFT>>>();
    gemm_inproj_tc<<<dim3(INNER / 128, LL / 128, BB), 256, SMEM_GEMM>>>(u, ipw, ipb);
    fftconv_kernel<<<dim3(NPAIR, BB), FNTH, SMEM_FFT>>>(bias, sw, sb);
    gemm_out_tc<<<dim3(DD / 128, LL / 128, BB), 256, SMEM_GEMM>>>(ow, ob, y);
}

// round 8
// speedup vs baseline: 1.1513x; 1.1513x over previous
#include <cuda_runtime.h>
#include <cuda_bf16.h>
#include <math.h>
#include <stdint.h>

// ---------------- problem constants ----------------
#define BB    2
#define LL    8192
#define N2    16384      // 2*L, FFT length = 4^7
#define DD    768
#define FF    768
#define ORDER 2
#define INNER 2304       // F*(ORDER+1)
#define NPAIR 384        // FF/2 channel pairs
#define FNTH  1024       // threads for FFT kernels

// padded smem layout for FFT data: +2 float2 per 64 elements
#define PD(i) ((i) + 2 * ((i) >> 6))
#define DATA_PAD 16896                       // PD(16383)+1 rounded up
#define SMEM_FFT ((DATA_PAD + N2 / 4) * 8)   // data + 4096 twiddles = 167936 B

// ---------------- scratch (static device memory; no allocation) ----------------
__device__ float2 d_h2 [(size_t)ORDER * NPAIR * N2];        // filter pairs: .x = ch 2i, .y = ch 2i+1
__device__ float2 d_hf [(size_t)ORDER * NPAIR * 2 * N2];    // spectra [o][pair][ch][p], dr4 order, (fft(h)+bias)/n
__device__ float  d_proj[(size_t)BB * INNER * LL];          // in-proj output, [b][c][l]
__device__ float  d_vout[(size_t)BB * FF * LL];             // final v, [b][f][l]

// ---------------- complex helpers ----------------
__device__ __forceinline__ float2 cadd(float2 a, float2 b) { return make_float2(a.x + b.x, a.y + b.y); }
__device__ __forceinline__ float2 csub(float2 a, float2 b) { return make_float2(a.x - b.x, a.y - b.y); }
__device__ __forceinline__ float2 cmul(float2 a, float2 b) {
    return make_float2(a.x * b.x - a.y * b.y, a.x * b.y + a.y * b.x);
}
__device__ __forceinline__ float2 cmulc(float2 a, float2 b) {   // a * conj(b)
    return make_float2(a.x * b.x + a.y * b.y, a.y * b.x - a.x * b.y);
}

// base-4 digit reversal of a 14-bit index (involution)
__device__ __forceinline__ int dr4(int p) {
    unsigned r = __brev((unsigned)p) >> 18;
    return (int)(((r & 0x2AAAu) >> 1) | ((r & 0x1555u) << 1));
}

// ---------------- radix-4 butterflies ----------------
__device__ __forceinline__ void bf4_fwd(float2& a, float2& b, float2& c, float2& d, float2 w1) {
    float2 w2 = cmul(w1, w1), w3 = cmul(w2, w1);
    float2 t0 = cadd(a, c), t1 = csub(a, c), t2 = cadd(b, d), t3 = csub(b, d);
    a = cadd(t0, t2);
    float2 X1 = make_float2(t1.x + t3.y, t1.y - t3.x);
    float2 X2 = csub(t0, t2);
    float2 X3 = make_float2(t1.x - t3.y, t1.y + t3.x);
    b = cmul(X1, w1); c = cmul(X2, w2); d = cmul(X3, w3);
}
__device__ __forceinline__ void bf4_fwd_nw(float2& a, float2& b, float2& c, float2& d) {
    float2 t0 = cadd(a, c), t1 = csub(a, c), t2 = cadd(b, d), t3 = csub(b, d);
    a = cadd(t0, t2);
    float2 X1 = make_float2(t1.x + t3.y, t1.y - t3.x);
    float2 X2 = csub(t0, t2);
    float2 X3 = make_float2(t1.x - t3.y, t1.y + t3.x);
    b = X1; c = X2; d = X3;
}
__device__ __forceinline__ void bf4_inv(float2& a, float2& b, float2& c, float2& d, float2 w1) {
    float2 w2 = cmul(w1, w1), w3 = cmul(w2, w1);
    float2 b1 = cmulc(b, w1), b2 = cmulc(c, w2), b3 = cmulc(d, w3);
    float2 s0 = cadd(a, b2), s1 = csub(a, b2), s2 = cadd(b1, b3), s3 = csub(b1, b3);
    a = cadd(s0, s2);
    b = make_float2(s1.x - s3.y, s1.y + s3.x);
    c = csub(s0, s2);
    d = make_float2(s1.x + s3.y, s1.y - s3.x);
}
__device__ __forceinline__ void bf4_inv_nw(float2& a, float2& b, float2& c, float2& d) {
    float2 s0 = cadd(a, c), s1 = csub(a, c), s2 = cadd(b, d), s3 = csub(b, d);
    a = cadd(s0, s2);
    b = make_float2(s1.x - s3.y, s1.y + s3.x);
    c = csub(s0, s2);
    d = make_float2(s1.x + s3.y, s1.y - s3.x);
}

__device__ __forceinline__ void build_twiddles4(float2* tw4, int tid) {
    #pragma unroll
    for (int i = 0; i < N2 / 4 / FNTH; i++) {
        int j = tid + i * FNTH;
        float x = -(float)j * (1.0f / 8192.0f);
        float s, c;
        sincospif(x, &s, &c);
        tw4[j] = make_float2(c, s);
    }
}

// ---------------- register-resident 16K FFT, 4 smem exchange phases ----------------
// forward DIF, natural -> dr4 order. On entry e[r] = D[tid + 1024r]. Result left in smem.
template <bool ZPAD>
__device__ __forceinline__ void fft16k_fwd_regs(float2* sm, const float2* tw, float2 e[16], int tid) {
    // P1: stages Q=4096, Q=1024 (ownership tid + 1024r)
    #pragma unroll
    for (int r0 = 0; r0 < 4; r0++) {
        float2 w1 = tw[tid + 1024 * r0];
        if (ZPAD) {   // e[8..15] known zero
            float2 a = e[r0], b = e[r0 + 4];
            float2 w2 = cmul(w1, w1), w3 = cmul(w2, w1);
            e[r0]      = cadd(a, b);
            e[r0 + 4]  = cmul(make_float2(a.x + b.y, a.y - b.x), w1);   // a - i b
            e[r0 + 8]  = cmul(csub(a, b), w2);
            e[r0 + 12] = cmul(make_float2(a.x - b.y, a.y + b.x), w3);   // a + i b
        } else {
            bf4_fwd(e[r0], e[r0 + 4], e[r0 + 8], e[r0 + 12], w1);
        }
    }
    {
        float2 w1 = tw[tid << 2];
        #pragma unroll
        for (int g = 0; g < 4; g++) bf4_fwd(e[4 * g], e[4 * g + 1], e[4 * g + 2], e[4 * g + 3], w1);
    }
    #pragma unroll
    for (int r = 0; r < 16; r++) sm[PD(tid + 1024 * r)] = e[r];
    __syncthreads();

    // P2: stages Q=256, Q=64 (ownership blk*1024 + off + 64r)
    {
        const int off  = tid & 63;
        const int base = ((tid >> 6) << 10) + off;
        #pragma unroll
        for (int r = 0; r < 16; r++) e[r] = sm[PD(base + 64 * r)];
        #pragma unroll
        for (int r0 = 0; r0 < 4; r0++)
            bf4_fwd(e[r0], e[r0 + 4], e[r0 + 8], e[r0 + 12], tw[(off + 64 * r0) << 4]);
        float2 w1 = tw[off << 6];
        #pragma unroll
        for (int g = 0; g < 4; g++) bf4_fwd(e[4 * g], e[4 * g + 1], e[4 * g + 2], e[4 * g + 3], w1);
        #pragma unroll
        for (int r = 0; r < 16; r++) sm[PD(base + 64 * r)] = e[r];
    }
    __syncthreads();

    // P3: stages Q=16, Q=4 (ownership seg*64 + 4r + c)
    {
        const int c4   = tid & 3;
        const int base = ((tid >> 2) << 6) + c4;
        #pragma unroll
        for (int r = 0; r < 16; r++) e[r] = sm[PD(base + 4 * r)];
        #pragma unroll
        for (int r0 = 0; r0 < 4; r0++)
            bf4_fwd(e[r0], e[r0 + 4], e[r0 + 8], e[r0 + 12], tw[(4 * r0 + c4) << 8]);
        float2 w1 = tw[c4 << 10];
        #pragma unroll
        for (int g = 0; g < 4; g++) bf4_fwd(e[4 * g], e[4 * g + 1], e[4 * g + 2], e[4 * g + 3], w1);
        #pragma unroll
        for (int r = 0; r < 16; r++) sm[PD(base + 4 * r)] = e[r];
    }
    __syncthreads();

    // P4: final stage Q=1 (no twiddle), float4 on 4-consecutive
    #pragma unroll
    for (int k = 0; k < 4; k++) {
        int si = PD(4 * (tid + 1024 * k));
        float4 lo = *(float4*)&sm[si];
        float4 hi = *(float4*)&sm[si + 2];
        float2 a = make_float2(lo.x, lo.y), b = make_float2(lo.z, lo.w);
        float2 c = make_float2(hi.x, hi.y), d = make_float2(hi.z, hi.w);
        bf4_fwd_nw(a, b, c, d);
        *(float4*)&sm[si]     = make_float4(a.x, a.y, b.x, b.y);
        *(float4*)&sm[si + 2] = make_float4(c.x, c.y, d.x, d.y);
    }
    __syncthreads();
}

// inverse DIT, dr4 -> natural order, unnormalized. Data starts in smem; result left in e[r] = D[tid + 1024r].
__device__ __forceinline__ void fft16k_inv_regs(float2* sm, const float2* tw, float2 e[16], int tid) {
    // I1: stage Q=1
    #pragma unroll
    for (int k = 0; k < 4; k++) {
        int si = PD(4 * (tid + 1024 * k));
        float4 lo = *(float4*)&sm[si];
        float4 hi = *(float4*)&sm[si + 2];
        float2 a = make_float2(lo.x, lo.y), b = make_float2(lo.z, lo.w);
        float2 c = make_float2(hi.x, hi.y), d = make_float2(hi.z, hi.w);
        bf4_inv_nw(a, b, c, d);
        *(float4*)&sm[si]     = make_float4(a.x, a.y, b.x, b.y);
        *(float4*)&sm[si + 2] = make_float4(c.x, c.y, d.x, d.y);
    }
    __syncthreads();

    // I2: stages Q=4, Q=16 (ownership seg*64 + 4r + c)
    {
        const int c4   = tid & 3;
        const int base = ((tid >> 2) << 6) + c4;
        #pragma unroll
        for (int r = 0; r < 16; r++) e[r] = sm[PD(base + 4 * r)];
        float2 w1 = tw[c4 << 10];
        #pragma unroll
        for (int g = 0; g < 4; g++) bf4_inv(e[4 * g], e[4 * g + 1], e[4 * g + 2], e[4 * g + 3], w1);
        #pragma unroll
        for (int r0 = 0; r0 < 4; r0++)
            bf4_inv(e[r0], e[r0 + 4], e[r0 + 8], e[r0 + 12], tw[(4 * r0 + c4) << 8]);
        #pragma unroll
        for (int r = 0; r < 16; r++) sm[PD(base + 4 * r)] = e[r];
    }
    __syncthreads();

    // I3: stages Q=64, Q=256 (ownership blk*1024 + off + 64r)
    {
        const int off  = tid & 63;
        const int base = ((tid >> 6) << 10) + off;
        #pragma unroll
        for (int r = 0; r < 16; r++) e[r] = sm[PD(base + 64 * r)];
        float2 w1 = tw[off << 6];
        #pragma unroll
        for (int g = 0; g < 4; g++) bf4_inv(e[4 * g], e[4 * g + 1], e[4 * g + 2], e[4 * g + 3], w1);
        #pragma unroll
        for (int r0 = 0; r0 < 4; r0++)
            bf4_inv(e[r0], e[r0 + 4], e[r0 + 8], e[r0 + 12], tw[(off + 64 * r0) << 4]);
        #pragma unroll
        for (int r = 0; r < 16; r++) sm[PD(base + 64 * r)] = e[r];
    }
    __syncthreads();

    // I4: stages Q=1024, Q=4096 (ownership tid + 1024r); result stays in regs
    #pragma unroll
    for (int r = 0; r < 16; r++) e[r] = sm[PD(tid + 1024 * r)];
    {
        float2 w1 = tw[tid << 2];
        #pragma unroll
        for (int g = 0; g < 4; g++) bf4_inv(e[4 * g], e[4 * g + 1], e[4 * g + 2], e[4 * g + 3], w1);
    }
    #pragma unroll
    for (int r0 = 0; r0 < 4; r0++)
        bf4_inv(e[r0], e[r0 + 4], e[r0 + 8], e[r0 + 12], tw[tid + 1024 * r0]);
}

__device__ __forceinline__ float scval(const float* __restrict__ row, int l,
                                       float w0, float w1, float w2, float bb) {
    float acc = bb + w1 * row[l];
    if (l > 0)      acc += w0 * row[l - 1];
    if (l < LL - 1) acc += w2 * row[l + 1];
    return acc;
}

// ---------------- tf32x3 MMA helpers ----------------
__device__ __forceinline__ void split_tf32(float x, uint32_t& hi, uint32_t& lo) {
    uint32_t xb = __float_as_uint(x);
    hi = xb & 0xFFFFE000u;
    float lof = x - __uint_as_float(hi);
    lo = __float_as_uint(lof) & 0xFFFFE000u;
}

__device__ __forceinline__ void mma_tf32(float* c, const uint32_t* a, const uint32_t* b) {
    asm volatile(
        "mma.sync.aligned.m16n8k8.row.col.f32.tf32.tf32.f32 "
        "{%0,%1,%2,%3}, {%4,%5,%6,%7}, {%8,%9}, {%0,%1,%2,%3};"
        : "+f"(c[0]), "+f"(c[1]), "+f"(c[2]), "+f"(c[3])
        : "r"(a[0]), "r"(a[1]), "r"(a[2]), "r"(a[3]), "r"(b[0]), "r"(b[1]));
}

// ---------------- kernel 1: filter MLP + modulation (pair-interleaved output) ----
__global__ __launch_bounds__(256) void hfilter_kernel(
    const float* __restrict__ w1, const float* __restrict__ b1,
    const float* __restrict__ w2, const float* __restrict__ b2,
    const float* __restrict__ decay)
{
    __shared__ float hid[16][64];
    const int p0  = blockIdx.x * 16;
    const int tid = threadIdx.x;

    for (int idx = tid; idx < 16 * 64; idx += 256) {
        int pp = idx >> 6;
        int u  = idx & 63;
        int p  = p0 + pp;
        float off = (p < LL) ? (float)p : (float)(p - N2);
        float t[9];
        t[0] = off * (1.0f / 8192.0f);
        const float step = (8192.0f - 4.0f) / 3.0f;
        #pragma unroll
        for (int i = 0; i < 4; i++) {
            float period = 4.0f + step * (float)i;
            float fr = 6.28318530717958647692f / period;
            float ph = off * fr;
            t[1 + i] = cosf(ph);
            t[5 + i] = sinf(ph);
        }
        float a = b1[u];
        #pragma unroll
        for (int k = 0; k < 9; k++) a += t[k] * w1[k * 64 + u];
        hid[pp][u] = sinf(a);
    }
    __syncthreads();

    for (int oc = tid; oc < ORDER * FF; oc += 256) {
        float acc[16];
        float bv = b2[oc];
        #pragma unroll
        for (int pp = 0; pp < 16; pp++) acc[pp] = bv;
        for (int k = 0; k < 64; k++) {
            float wv = w2[k * (ORDER * FF) + oc];
            #pragma unroll
            for (int pp = 0; pp < 16; pp++) acc[pp] += hid[pp][k] * wv;
        }
        float dec = fabsf(decay[oc]);
        int o = oc / FF, f = oc - o * FF;
        float* dst = (float*)(d_h2 + ((size_t)(o * NPAIR + (f >> 1))) * N2 + p0) + (f & 1);
        #pragma unroll
        for (int pp = 0; pp < 16; pp++) {
            int p = p0 + pp;
            float mod = (p < LL) ? (float)p * (1.0f / 8191.0f)
                                 : (float)(N2 - 1 - p) * (1.0f / 8191.0f);
            dst[2 * pp] = acc[pp] * expf(-mod * dec);
        }
    }
}

// ---------------- kernel 2: paired filter FFT (register radix-4, bias folded) ------
__global__ __launch_bounds__(FNTH) void hfft_kernel(const float* __restrict__ bias) {
    extern __shared__ float2 smem_f2[];
    float2* sm = smem_f2;
    float2* tw = smem_f2 + DATA_PAD;
    const int cp  = blockIdx.x;
    const int tid = threadIdx.x;

    build_twiddles4(tw, tid);
    float2 e[16];
    const float2* src = d_h2 + (size_t)cp * N2;
    #pragma unroll
    for (int r = 0; r < 16; r++) e[r] = src[tid + 1024 * r];
    __syncthreads();

    fft16k_fwd_regs<false>(sm, tw, e, tid);

    // unpack two Hermitian spectra (dr4 domain), scale 1/n, fold bias/n into DC-shift
    const int o  = cp / NPAIR;
    const int f0 = 2 * (cp % NPAIR);
    const float c0 = bias[o * FF + f0]     * (1.0f / (float)N2);
    const float c1 = bias[o * FF + f0 + 1] * (1.0f / (float)N2);
    const float s  = 0.5f / (float)N2;
    float2* hf0 = d_hf + (size_t)(cp * 2 + 0) * N2;
    float2* hf1 = d_hf + (size_t)(cp * 2 + 1) * N2;
    #pragma unroll
    for (int i = 0; i < 16; i++) {
        int p  = tid + 1024 * i;
        int k  = dr4(p);
        int km = (N2 - k) & (N2 - 1);
        int pm = dr4(km);
        if (p <= pm) {
            float2 z1 = sm[PD(p)];
            float2 z2 = sm[PD(pm)];
            float2 H0 = make_float2(s * (z1.x + z2.x) + c0,  s * (z1.y - z2.y));
            float2 H1 = make_float2(s * (z1.y + z2.y) + c1, -s * (z1.x - z2.x));
            hf0[p]  = H0;
            hf1[p]  = H1;
            hf0[pm] = make_float2(H0.x, -H0.y);
            hf1[pm] = make_float2(H1.x, -H1.y);
        }
    }
}

// ---------------- kernel 3: in-projection GEMM, tf32x3 (round-6 version) ----------
__global__ __launch_bounds__(256) void gemm_inproj_tc(
    const float* __restrict__ U, const float* __restrict__ W,
    const float* __restrict__ bias)
{
    __shared__ float As[32][132];
    __shared__ float Bs[32][132];
    const int b  = blockIdx.z;
    const int c0 = blockIdx.x * 128;
    const int l0 = blockIdx.y * 128;
    const float* Ub = U + (size_t)b * LL * DD;
    float* Cb = d_proj + (size_t)b * INNER * LL;

    const int tid    = threadIdx.x;
    const int wid    = tid >> 5;
    const int lane   = tid & 31;
    const int warp_m = wid >> 2;
    const int warp_n = wid & 3;
    const int q      = lane >> 2;
    const int r      = lane & 3;

    float acc[4][4][4];
    #pragma unroll
    for (int mt = 0; mt < 4; mt++)
        #pragma unroll
        for (int nt = 0; nt < 4; nt++)
            #pragma unroll
            for (int j = 0; j < 4; j++) acc[mt][nt][j] = 0.0f;

    for (int k0 = 0; k0 < DD; k0 += 32) {
        #pragma unroll
        for (int i = 0; i < 4; i++) {
            int slot = tid + i * 256;
            int m  = slot >> 3;
            int kq = (slot & 7) * 4;
            float4 v = *(const float4*)(Ub + (size_t)(l0 + m) * DD + k0 + kq);
            As[kq + 0][m] = v.x;
            As[kq + 1][m] = v.y;
            As[kq + 2][m] = v.z;
            As[kq + 3][m] = v.w;
            int nq = (slot & 31) * 4;
            int kk = slot >> 5;
            float4 w4 = *(const float4*)(W + (size_t)(k0 + kk) * INNER + c0 + nq);
            *(float4*)&Bs[kk][nq] = w4;
        }
        __syncthreads();

        #pragma unroll
        for (int s = 0; s < 4; s++) {
            const int kb = s * 8;
            uint32_t bh[4][2], bl[4][2];
            #pragma unroll
            for (int nt = 0; nt < 4; nt++) {
                int n = warp_n * 32 + nt * 8 + q;
                split_tf32(Bs[kb + r][n],     bh[nt][0], bl[nt][0]);
                split_tf32(Bs[kb + 4 + r][n], bh[nt][1], bl[nt][1]);
            }
            #pragma unroll
            for (int mt = 0; mt < 4; mt++) {
                int m = warp_m * 64 + mt * 16 + q;
                uint32_t ah[4], al[4];
                split_tf32(As[kb + r][m],         ah[0], al[0]);
                split_tf32(As[kb + r][m + 8],     ah[1], al[1]);
                split_tf32(As[kb + 4 + r][m],     ah[2], al[2]);
                split_tf32(As[kb + 4 + r][m + 8], ah[3], al[3]);
                #pragma unroll
                for (int nt = 0; nt < 4; nt++) {
                    mma_tf32(acc[mt][nt], ah, bh[nt]);
                    mma_tf32(acc[mt][nt], ah, bl[nt]);
                    mma_tf32(acc[mt][nt], al, bh[nt]);
                }
            }
        }
        __syncthreads();
    }

    float* st = &As[0][0];
    for (int p = 0; p < 4; p++) {
        if (warp_n == p) {
            #pragma unroll
            for (int mt = 0; mt < 4; mt++)
                #pragma unroll
                for (int nt = 0; nt < 4; nt++) {
                    int m = warp_m * 64 + mt * 16 + q;
                    int n = nt * 8 + 2 * r;
                    st[(n    ) * 129 + m    ] = acc[mt][nt][0];
                    st[(n + 1) * 129 + m    ] = acc[mt][nt][1];
                    st[(n    ) * 129 + m + 8] = acc[mt][nt][2];
                    st[(n + 1) * 129 + m + 8] = acc[mt][nt][3];
                }
        }
        __syncthreads();
        int row = tid >> 3;
        int cq  = tid & 7;
        int c   = c0 + p * 32 + row;
        float bb = bias[c];
        float* dst = Cb + (size_t)c * LL + l0;
        #pragma unroll
        for (int ii = 0; ii < 4; ii++) {
            int mq = cq + 8 * ii;
            float4 v = make_float4(st[row * 129 + mq * 4 + 0] + bb,
                                   st[row * 129 + mq * 4 + 1] + bb,
                                   st[row * 129 + mq * 4 + 2] + bb,
                                   st[row * 129 + mq * 4 + 3] + bb);
            *(float4*)(dst + mq * 4) = v;
        }
        __syncthreads();
    }
}

// ---------------- kernel 4: fused FFT conv (register radix-4, bias pre-folded) ----
__global__ __launch_bounds__(FNTH) void fftconv_kernel(
    const float* __restrict__ sw, const float* __restrict__ sb)
{
    extern __shared__ float2 smem_f2[];
    float2* sm = smem_f2;
    float2* tw = smem_f2 + DATA_PAD;
    const int pr  = blockIdx.x;
    const int b   = blockIdx.y;
    const int tid = threadIdx.x;
    const int f0  = 2 * pr;
    const int f1  = 2 * pr + 1;

    build_twiddles4(tw, tid);

    float2 e[16];
    {
        const float* r0 = d_proj + ((size_t)b * INNER + f0) * LL;
        const float* r1 = d_proj + ((size_t)b * INNER + f1) * LL;
        float a0 = sw[f0], a1 = sw[INNER + f0], a2 = sw[2 * INNER + f0], ab = sb[f0];
        float c0 = sw[f1], c1 = sw[INNER + f1], c2 = sw[2 * INNER + f1], cb = sb[f1];
        #pragma unroll
        for (int i = 0; i < 8; i++) {
            int l = tid + 1024 * i;
            e[i] = make_float2(scval(r0, l, a0, a1, a2, ab),
                               scval(r1, l, c0, c1, c2, cb));
        }
        #pragma unroll
        for (int i = 8; i < 16; i++) e[i] = make_float2(0.0f, 0.0f);
    }
    __syncthreads();   // twiddles ready

    #pragma unroll 1
    for (int o = 0; o < ORDER; o++) {
        fft16k_fwd_regs<true>(sm, tw, e, tid);

        // spectral: paired Hermitian unpack, per-channel Heff multiply, repack (dr4 domain)
        const float2* hf0 = d_hf + (size_t)((o * NPAIR + pr) * 2 + 0) * N2;
        const float2* hf1 = d_hf + (size_t)((o * NPAIR + pr) * 2 + 1) * N2;
        #pragma unroll
        for (int i = 0; i < 16; i++) {
            int p  = tid + 1024 * i;
            int k  = dr4(p);
            int km = (N2 - k) & (N2 - 1);
            int pm = dr4(km);
            if (p <= pm) {
                float2 z1 = sm[PD(p)];
                float2 z2 = sm[PD(pm)];
                float2 V0 = make_float2(0.5f * (z1.x + z2.x),  0.5f * (z1.y - z2.y));
                float2 V1 = make_float2(0.5f * (z1.y + z2.y), -0.5f * (z1.x - z2.x));
                float2 Y0 = cmul(V0, hf0[p]);
                float2 Y1 = cmul(V1, hf1[p]);
                sm[PD(p)]  = make_float2(Y0.x - Y1.y, Y0.y + Y1.x);
                sm[PD(pm)] = make_float2(Y0.x + Y1.y, Y1.x - Y0.y);
            }
        }
        __syncthreads();

        fft16k_inv_regs(sm, tw, e, tid);

        // v_new = y_eff * gate   (bias term already folded into Heff)
        {
            const int g0c = (1 + o) * FF + f0;
            const int g1c = (1 + o) * FF + f1;
            const float* g0r = d_proj + ((size_t)b * INNER + g0c) * LL;
            const float* g1r = d_proj + ((size_t)b * INNER + g1c) * LL;
            float ga0 = sw[g0c], ga1 = sw[INNER + g0c], ga2 = sw[2 * INNER + g0c], gab = sb[g0c];
            float gc0 = sw[g1c], gc1 = sw[INNER + g1c], gc2 = sw[2 * INNER + g1c], gcb = sb[g1c];
            #pragma unroll
            for (int i = 0; i < 8; i++) {
                int l = tid + 1024 * i;
                float g0 = scval(g0r, l, ga0, ga1, ga2, gab);
                float g1 = scval(g1r, l, gc0, gc1, gc2, gcb);
                e[i].x *= g0;
                e[i].y *= g1;
            }
            #pragma unroll
            for (int i = 8; i < 16; i++) e[i] = make_float2(0.0f, 0.0f);
        }
        __syncthreads();   // protect sm before next order's P1 stores
    }

    float* dst0 = d_vout + ((size_t)b * FF + f0) * LL;
    float* dst1 = d_vout + ((size_t)b * FF + f1) * LL;
    #pragma unroll
    for (int i = 0; i < 8; i++) {
        int l = tid + 1024 * i;
        dst0[l] = e[i].x;
        dst1[l] = e[i].y;
    }
}

// ---------------- kernel 5: output GEMM, tf32x3 (round-6 version) ----------------
__global__ __launch_bounds__(256) void gemm_out_tc(
    const float* __restrict__ W, const float* __restrict__ bias,
    float* __restrict__ Y)
{
    __shared__ float As[32][132];
    __shared__ float Bs[32][132];
    const int b  = blockIdx.z;
    const int d0 = blockIdx.x * 128;
    const int l0 = blockIdx.y * 128;
    const float* Vb = d_vout + (size_t)b * FF * LL;
    float* Yb = Y + (size_t)b * LL * DD;

    const int tid    = threadIdx.x;
    const int wid    = tid >> 5;
    const int lane   = tid & 31;
    const int warp_m = wid >> 2;
    const int warp_n = wid & 3;
    const int q      = lane >> 2;
    const int r      = lane & 3;

    float acc[4][4][4];
    #pragma unroll
    for (int mt = 0; mt < 4; mt++)
        #pragma unroll
        for (int nt = 0; nt < 4; nt++)
            #pragma unroll
            for (int j = 0; j < 4; j++) acc[mt][nt][j] = 0.0f;

    for (int k0 = 0; k0 < FF; k0 += 32) {
        #pragma unroll
        for (int i = 0; i < 4; i++) {
            int slot = tid + i * 256;
            int mq = (slot & 31) * 4;
            int kk = slot >> 5;
            float4 v = *(const float4*)(Vb + (size_t)(k0 + kk) * LL + l0 + mq);
            *(float4*)&As[kk][mq] = v;
            float4 w4 = *(const float4*)(W + (size_t)(k0 + kk) * DD + d0 + mq);
            *(float4*)&Bs[kk][mq] = w4;
        }
        __syncthreads();

        #pragma unroll
        for (int s = 0; s < 4; s++) {
            const int kb = s * 8;
            uint32_t bh[4][2], bl[4][2];
            #pragma unroll
            for (int nt = 0; nt < 4; nt++) {
                int n = warp_n * 32 + nt * 8 + q;
                split_tf32(Bs[kb + r][n],     bh[nt][0], bl[nt][0]);
                split_tf32(Bs[kb + 4 + r][n], bh[nt][1], bl[nt][1]);
            }
            #pragma unroll
            for (int mt = 0; mt < 4; mt++) {
                int m = warp_m * 64 + mt * 16 + q;
                uint32_t ah[4], al[4];
                split_tf32(As[kb + r][m],         ah[0], al[0]);
                split_tf32(As[kb + r][m + 8],     ah[1], al[1]);
                split_tf32(As[kb + 4 + r][m],     ah[2], al[2]);
                split_tf32(As[kb + 4 + r][m + 8], ah[3], al[3]);
                #pragma unroll
                for (int nt = 0; nt < 4; nt++) {
                    mma_tf32(acc[mt][nt], ah, bh[nt]);
                    mma_tf32(acc[mt][nt], ah, bl[nt]);
                    mma_tf32(acc[mt][nt], al, bh[nt]);
                }
            }
        }
        __syncthreads();
    }

    #pragma unroll
    for (int mt = 0; mt < 4; mt++) {
        #pragma unroll
        for (int nt = 0; nt < 4; nt++) {
            int n = d0 + warp_n * 32 + nt * 8 + 2 * r;
            float b0v = bias[n], b1v = bias[n + 1];
            int m = l0 + warp_m * 64 + mt * 16 + q;
            float2 o0 = make_float2(acc[mt][nt][0] + b0v, acc[mt][nt][1] + b1v);
            float2 o1 = make_float2(acc[mt][nt][2] + b0v, acc[mt][nt][3] + b1v);
            *(float2*)(Yb + (size_t)m * DD + n)       = o0;
            *(float2*)(Yb + (size_t)(m + 8) * DD + n) = o1;
        }
    }
}

// ---------------- launch ----------------
extern "C" void kernel_launch(void* const* d_in, const int* in_sizes, int n_in,
                              void* d_out, int out_size) {
    const float* u     = (const float*)d_in[0];
    const float* fw1   = (const float*)d_in[1];
    const float* fb1   = (const float*)d_in[2];
    const float* fw2   = (const float*)d_in[3];
    const float* fb2   = (const float*)d_in[4];
    const float* decay = (const float*)d_in[5];
    const float* bias  = (const float*)d_in[6];
    const float* ipw   = (const float*)d_in[7];
    const float* ipb   = (const float*)d_in[8];
    const float* sw    = (const float*)d_in[9];
    const float* sb    = (const float*)d_in[10];
    const float* ow    = (const float*)d_in[11];
    const float* ob    = (const float*)d_in[12];
    float* y = (float*)d_out;

    cudaFuncSetAttribute(hfft_kernel,    cudaFuncAttributeMaxDynamicSharedMemorySize, SMEM_FFT);
    cudaFuncSetAttribute(fftconv_kernel, cudaFuncAttributeMaxDynamicSharedMemorySize, SMEM_FFT);

    hfilter_kernel<<<N2 / 16, 256>>>(fw1, fb1, fw2, fb2, decay);
    hfft_kernel<<<ORDER * NPAIR, FNTH, SMEM_FFT>>>(bias);
    gemm_inproj_tc<<<dim3(INNER / 128, LL / 128, BB), 256>>>(u, ipw, ipb);
    fftconv_kernel<<<dim3(NPAIR, BB), FNTH, SMEM_FFT>>>(sw, sb);
    gemm_out_tc<<<dim3(DD / 128, LL / 128, BB), 256>>>(ow, ob, y);
}

// round 9
// speedup vs baseline: 1.5903x; 1.3813x over previous
#include <cuda_runtime.h>
#include <cuda_bf16.h>
#include <math.h>
#include <stdint.h>

// ---------------- problem constants ----------------
#define BB    2
#define LL    8192
#define N2    16384      // 2*L, FFT length = 4^7
#define DD    768
#define FF    768
#define ORDER 2
#define INNER 2304       // F*(ORDER+1)
#define NPAIR 384        // FF/2 channel pairs
#define FNTH  1024       // threads for FFT kernels

// padded smem layout for FFT data: +2 float2 per 64 elements
#define PD(i) ((i) + 2 * ((i) >> 6))
#define DATA_PAD 16896
#define SMEM_FFT ((DATA_PAD + N2 / 4) * 8)   // 167936 B

// ---------------- scratch (static device memory; no allocation) ----------------
__device__ float2 d_h2 [(size_t)ORDER * NPAIR * N2];
__device__ float2 d_hf [(size_t)ORDER * NPAIR * 2 * N2];    // (fft(h)+bias)/n, dr4 order
__device__ float  d_proj[(size_t)BB * INNER * LL];
__device__ float  d_vout[(size_t)BB * FF * LL];

// ---------------- complex helpers ----------------
__device__ __forceinline__ float2 cadd(float2 a, float2 b) { return make_float2(a.x + b.x, a.y + b.y); }
__device__ __forceinline__ float2 csub(float2 a, float2 b) { return make_float2(a.x - b.x, a.y - b.y); }
__device__ __forceinline__ float2 cmul(float2 a, float2 b) {
    return make_float2(a.x * b.x - a.y * b.y, a.x * b.y + a.y * b.x);
}
__device__ __forceinline__ float2 cmulc(float2 a, float2 b) {
    return make_float2(a.x * b.x + a.y * b.y, a.y * b.x - a.x * b.y);
}

__device__ __forceinline__ int dr4(int p) {
    unsigned r = __brev((unsigned)p) >> 18;
    return (int)(((r & 0x2AAAu) >> 1) | ((r & 0x1555u) << 1));
}

// ---------------- radix-4 butterflies ----------------
__device__ __forceinline__ void bf4_fwd(float2& a, float2& b, float2& c, float2& d, float2 w1) {
    float2 w2 = cmul(w1, w1), w3 = cmul(w2, w1);
    float2 t0 = cadd(a, c), t1 = csub(a, c), t2 = cadd(b, d), t3 = csub(b, d);
    a = cadd(t0, t2);
    float2 X1 = make_float2(t1.x + t3.y, t1.y - t3.x);
    float2 X2 = csub(t0, t2);
    float2 X3 = make_float2(t1.x - t3.y, t1.y + t3.x);
    b = cmul(X1, w1); c = cmul(X2, w2); d = cmul(X3, w3);
}
__device__ __forceinline__ void bf4_fwd_nw(float2& a, float2& b, float2& c, float2& d) {
    float2 t0 = cadd(a, c), t1 = csub(a, c), t2 = cadd(b, d), t3 = csub(b, d);
    a = cadd(t0, t2);
    float2 X1 = make_float2(t1.x + t3.y, t1.y - t3.x);
    float2 X2 = csub(t0, t2);
    float2 X3 = make_float2(t1.x - t3.y, t1.y + t3.x);
    b = X1; c = X2; d = X3;
}
__device__ __forceinline__ void bf4_inv(float2& a, float2& b, float2& c, float2& d, float2 w1) {
    float2 w2 = cmul(w1, w1), w3 = cmul(w2, w1);
    float2 b1 = cmulc(b, w1), b2 = cmulc(c, w2), b3 = cmulc(d, w3);
    float2 s0 = cadd(a, b2), s1 = csub(a, b2), s2 = cadd(b1, b3), s3 = csub(b1, b3);
    a = cadd(s0, s2);
    b = make_float2(s1.x - s3.y, s1.y + s3.x);
    c = csub(s0, s2);
    d = make_float2(s1.x + s3.y, s1.y - s3.x);
}
__device__ __forceinline__ void bf4_inv_nw(float2& a, float2& b, float2& c, float2& d) {
    float2 s0 = cadd(a, c), s1 = csub(a, c), s2 = cadd(b, d), s3 = csub(b, d);
    a = cadd(s0, s2);
    b = make_float2(s1.x - s3.y, s1.y + s3.x);
    c = csub(s0, s2);
    d = make_float2(s1.x + s3.y, s1.y - s3.x);
}

__device__ __forceinline__ void build_twiddles4(float2* tw4, int tid) {
    #pragma unroll
    for (int i = 0; i < N2 / 4 / FNTH; i++) {
        int j = tid + i * FNTH;
        float x = -(float)j * (1.0f / 8192.0f);
        float s, c;
        sincospif(x, &s, &c);
        tw4[j] = make_float2(c, s);
    }
}

// ---------------- register-resident 16K FFT (round-8, unchanged) ----------------
template <bool ZPAD>
__device__ __forceinline__ void fft16k_fwd_regs(float2* sm, const float2* tw, float2 e[16], int tid) {
    #pragma unroll
    for (int r0 = 0; r0 < 4; r0++) {
        float2 w1 = tw[tid + 1024 * r0];
        if (ZPAD) {
            float2 a = e[r0], b = e[r0 + 4];
            float2 w2 = cmul(w1, w1), w3 = cmul(w2, w1);
            e[r0]      = cadd(a, b);
            e[r0 + 4]  = cmul(make_float2(a.x + b.y, a.y - b.x), w1);
            e[r0 + 8]  = cmul(csub(a, b), w2);
            e[r0 + 12] = cmul(make_float2(a.x - b.y, a.y + b.x), w3);
        } else {
            bf4_fwd(e[r0], e[r0 + 4], e[r0 + 8], e[r0 + 12], w1);
        }
    }
    {
        float2 w1 = tw[tid << 2];
        #pragma unroll
        for (int g = 0; g < 4; g++) bf4_fwd(e[4 * g], e[4 * g + 1], e[4 * g + 2], e[4 * g + 3], w1);
    }
    #pragma unroll
    for (int r = 0; r < 16; r++) sm[PD(tid + 1024 * r)] = e[r];
    __syncthreads();

    {
        const int off  = tid & 63;
        const int base = ((tid >> 6) << 10) + off;
        #pragma unroll
        for (int r = 0; r < 16; r++) e[r] = sm[PD(base + 64 * r)];
        #pragma unroll
        for (int r0 = 0; r0 < 4; r0++)
            bf4_fwd(e[r0], e[r0 + 4], e[r0 + 8], e[r0 + 12], tw[(off + 64 * r0) << 4]);
        float2 w1 = tw[off << 6];
        #pragma unroll
        for (int g = 0; g < 4; g++) bf4_fwd(e[4 * g], e[4 * g + 1], e[4 * g + 2], e[4 * g + 3], w1);
        #pragma unroll
        for (int r = 0; r < 16; r++) sm[PD(base + 64 * r)] = e[r];
    }
    __syncthreads();

    {
        const int c4   = tid & 3;
        const int base = ((tid >> 2) << 6) + c4;
        #pragma unroll
        for (int r = 0; r < 16; r++) e[r] = sm[PD(base + 4 * r)];
        #pragma unroll
        for (int r0 = 0; r0 < 4; r0++)
            bf4_fwd(e[r0], e[r0 + 4], e[r0 + 8], e[r0 + 12], tw[(4 * r0 + c4) << 8]);
        float2 w1 = tw[c4 << 10];
        #pragma unroll
        for (int g = 0; g < 4; g++) bf4_fwd(e[4 * g], e[4 * g + 1], e[4 * g + 2], e[4 * g + 3], w1);
        #pragma unroll
        for (int r = 0; r < 16; r++) sm[PD(base + 4 * r)] = e[r];
    }
    __syncthreads();

    #pragma unroll
    for (int k = 0; k < 4; k++) {
        int si = PD(4 * (tid + 1024 * k));
        float4 lo = *(float4*)&sm[si];
        float4 hi = *(float4*)&sm[si + 2];
        float2 a = make_float2(lo.x, lo.y), b = make_float2(lo.z, lo.w);
        float2 c = make_float2(hi.x, hi.y), d = make_float2(hi.z, hi.w);
        bf4_fwd_nw(a, b, c, d);
        *(float4*)&sm[si]     = make_float4(a.x, a.y, b.x, b.y);
        *(float4*)&sm[si + 2] = make_float4(c.x, c.y, d.x, d.y);
    }
    __syncthreads();
}

__device__ __forceinline__ void fft16k_inv_regs(float2* sm, const float2* tw, float2 e[16], int tid) {
    #pragma unroll
    for (int k = 0; k < 4; k++) {
        int si = PD(4 * (tid + 1024 * k));
        float4 lo = *(float4*)&sm[si];
        float4 hi = *(float4*)&sm[si + 2];
        float2 a = make_float2(lo.x, lo.y), b = make_float2(lo.z, lo.w);
        float2 c = make_float2(hi.x, hi.y), d = make_float2(hi.z, hi.w);
        bf4_inv_nw(a, b, c, d);
        *(float4*)&sm[si]     = make_float4(a.x, a.y, b.x, b.y);
        *(float4*)&sm[si + 2] = make_float4(c.x, c.y, d.x, d.y);
    }
    __syncthreads();

    {
        const int c4   = tid & 3;
        const int base = ((tid >> 2) << 6) + c4;
        #pragma unroll
        for (int r = 0; r < 16; r++) e[r] = sm[PD(base + 4 * r)];
        float2 w1 = tw[c4 << 10];
        #pragma unroll
        for (int g = 0; g < 4; g++) bf4_inv(e[4 * g], e[4 * g + 1], e[4 * g + 2], e[4 * g + 3], w1);
        #pragma unroll
        for (int r0 = 0; r0 < 4; r0++)
            bf4_inv(e[r0], e[r0 + 4], e[r0 + 8], e[r0 + 12], tw[(4 * r0 + c4) << 8]);
        #pragma unroll
        for (int r = 0; r < 16; r++) sm[PD(base + 4 * r)] = e[r];
    }
    __syncthreads();

    {
        const int off  = tid & 63;
        const int base = ((tid >> 6) << 10) + off;
        #pragma unroll
        for (int r = 0; r < 16; r++) e[r] = sm[PD(base + 64 * r)];
        float2 w1 = tw[off << 6];
        #pragma unroll
        for (int g = 0; g < 4; g++) bf4_inv(e[4 * g], e[4 * g + 1], e[4 * g + 2], e[4 * g + 3], w1);
        #pragma unroll
        for (int r0 = 0; r0 < 4; r0++)
            bf4_inv(e[r0], e[r0 + 4], e[r0 + 8], e[r0 + 12], tw[(off + 64 * r0) << 4]);
        #pragma unroll
        for (int r = 0; r < 16; r++) sm[PD(base + 64 * r)] = e[r];
    }
    __syncthreads();

    #pragma unroll
    for (int r = 0; r < 16; r++) e[r] = sm[PD(tid + 1024 * r)];
    {
        float2 w1 = tw[tid << 2];
        #pragma unroll
        for (int g = 0; g < 4; g++) bf4_inv(e[4 * g], e[4 * g + 1], e[4 * g + 2], e[4 * g + 3], w1);
    }
    #pragma unroll
    for (int r0 = 0; r0 < 4; r0++)
        bf4_inv(e[r0], e[r0 + 4], e[r0 + 8], e[r0 + 12], tw[tid + 1024 * r0]);
}

__device__ __forceinline__ float scval(const float* __restrict__ row, int l,
                                       float w0, float w1, float w2, float bb) {
    float acc = bb + w1 * row[l];
    if (l > 0)      acc += w0 * row[l - 1];
    if (l < LL - 1) acc += w2 * row[l + 1];
    return acc;
}

// ---------------- bf16x3 MMA helpers ----------------
// pack x into (bf16_hi << 16) | bf16_lo, where x ~= hi + lo
__device__ __forceinline__ uint32_t bsplit(float x) {
    __nv_bfloat16 h = __float2bfloat16_rn(x);
    float fh = __bfloat162float(h);
    __nv_bfloat16 l = __float2bfloat16_rn(x - fh);
    return ((uint32_t)__bfloat16_as_ushort(h) << 16) | (uint32_t)__bfloat16_as_ushort(l);
}
// build bf16x2 (k-even in low, k-odd in high) from two packed words
#define PHI(p0, p1) __byte_perm((p0), (p1), 0x7632)
#define PLO(p0, p1) __byte_perm((p0), (p1), 0x5410)

__device__ __forceinline__ void mma_bf16(float* c, const uint32_t* a, const uint32_t* b) {
    asm volatile(
        "mma.sync.aligned.m16n8k16.row.col.f32.bf16.bf16.f32 "
        "{%0,%1,%2,%3}, {%4,%5,%6,%7}, {%8,%9}, {%0,%1,%2,%3};"
        : "+f"(c[0]), "+f"(c[1]), "+f"(c[2]), "+f"(c[3])
        : "r"(a[0]), "r"(a[1]), "r"(a[2]), "r"(a[3]), "r"(b[0]), "r"(b[1]));
}

// ---------------- kernel 1: filter MLP + modulation ----------------
__global__ __launch_bounds__(256) void hfilter_kernel(
    const float* __restrict__ w1, const float* __restrict__ b1,
    const float* __restrict__ w2, const float* __restrict__ b2,
    const float* __restrict__ decay)
{
    __shared__ float hid[16][64];
    const int p0  = blockIdx.x * 16;
    const int tid = threadIdx.x;

    for (int idx = tid; idx < 16 * 64; idx += 256) {
        int pp = idx >> 6;
        int u  = idx & 63;
        int p  = p0 + pp;
        float off = (p < LL) ? (float)p : (float)(p - N2);
        float t[9];
        t[0] = off * (1.0f / 8192.0f);
        const float step = (8192.0f - 4.0f) / 3.0f;
        #pragma unroll
        for (int i = 0; i < 4; i++) {
            float period = 4.0f + step * (float)i;
            float fr = 6.28318530717958647692f / period;
            float ph = off * fr;
            t[1 + i] = cosf(ph);
            t[5 + i] = sinf(ph);
        }
        float a = b1[u];
        #pragma unroll
        for (int k = 0; k < 9; k++) a += t[k] * w1[k * 64 + u];
        hid[pp][u] = sinf(a);
    }
    __syncthreads();

    for (int oc = tid; oc < ORDER * FF; oc += 256) {
        float acc[16];
        float bv = b2[oc];
        #pragma unroll
        for (int pp = 0; pp < 16; pp++) acc[pp] = bv;
        for (int k = 0; k < 64; k++) {
            float wv = w2[k * (ORDER * FF) + oc];
            #pragma unroll
            for (int pp = 0; pp < 16; pp++) acc[pp] += hid[pp][k] * wv;
        }
        float dec = fabsf(decay[oc]);
        int o = oc / FF, f = oc - o * FF;
        float* dst = (float*)(d_h2 + ((size_t)(o * NPAIR + (f >> 1))) * N2 + p0) + (f & 1);
        #pragma unroll
        for (int pp = 0; pp < 16; pp++) {
            int p = p0 + pp;
            float mod = (p < LL) ? (float)p * (1.0f / 8191.0f)
                                 : (float)(N2 - 1 - p) * (1.0f / 8191.0f);
            dst[2 * pp] = acc[pp] * expf(-mod * dec);
        }
    }
}

// ---------------- kernel 2: paired filter FFT (register radix-4, bias folded) ----
__global__ __launch_bounds__(FNTH) void hfft_kernel(const float* __restrict__ bias) {
    extern __shared__ float2 smem_f2[];
    float2* sm = smem_f2;
    float2* tw = smem_f2 + DATA_PAD;
    const int cp  = blockIdx.x;
    const int tid = threadIdx.x;

    build_twiddles4(tw, tid);
    float2 e[16];
    const float2* src = d_h2 + (size_t)cp * N2;
    #pragma unroll
    for (int r = 0; r < 16; r++) e[r] = src[tid + 1024 * r];
    __syncthreads();

    fft16k_fwd_regs<false>(sm, tw, e, tid);

    const int o  = cp / NPAIR;
    const int f0 = 2 * (cp % NPAIR);
    const float c0 = bias[o * FF + f0]     * (1.0f / (float)N2);
    const float c1 = bias[o * FF + f0 + 1] * (1.0f / (float)N2);
    const float s  = 0.5f / (float)N2;
    float2* hf0 = d_hf + (size_t)(cp * 2 + 0) * N2;
    float2* hf1 = d_hf + (size_t)(cp * 2 + 1) * N2;
    #pragma unroll
    for (int i = 0; i < 16; i++) {
        int p  = tid + 1024 * i;
        int k  = dr4(p);
        int km = (N2 - k) & (N2 - 1);
        int pm = dr4(km);
        if (p <= pm) {
            float2 z1 = sm[PD(p)];
            float2 z2 = sm[PD(pm)];
            float2 H0 = make_float2(s * (z1.x + z2.x) + c0,  s * (z1.y - z2.y));
            float2 H1 = make_float2(s * (z1.y + z2.y) + c1, -s * (z1.x - z2.x));
            hf0[p]  = H0;
            hf1[p]  = H1;
            hf0[pm] = make_float2(H0.x, -H0.y);
            hf1[pm] = make_float2(H1.x, -H1.y);
        }
    }
}

// ---------------- kernel 3: in-projection GEMM, bf16x3 m16n8k16 ----------------
// C[b,c,l] = sum_d U[b,l,d]*W[d,c] + bias[c]  (output transposed [c][l])
__global__ __launch_bounds__(256) void gemm_inproj_tc(
    const float* __restrict__ U, const float* __restrict__ W,
    const float* __restrict__ bias)
{
    __shared__ uint32_t As[32][132];   // [k][m], packed (bf16hi<<16)|bf16lo
    __shared__ uint32_t Bs[32][132];   // [k][n]
    const int b  = blockIdx.z;
    const int c0 = blockIdx.x * 128;
    const int l0 = blockIdx.y * 128;
    const float* Ub = U + (size_t)b * LL * DD;
    float* Cb = d_proj + (size_t)b * INNER * LL;

    const int tid    = threadIdx.x;
    const int wid    = tid >> 5;
    const int lane   = tid & 31;
    const int warp_m = wid >> 2;
    const int warp_n = wid & 3;
    const int q      = lane >> 2;
    const int r      = lane & 3;

    float acc[4][4][4];
    #pragma unroll
    for (int mt = 0; mt < 4; mt++)
        #pragma unroll
        for (int nt = 0; nt < 4; nt++)
            #pragma unroll
            for (int j = 0; j < 4; j++) acc[mt][nt][j] = 0.0f;

    for (int k0 = 0; k0 < DD; k0 += 32) {
        #pragma unroll
        for (int i = 0; i < 4; i++) {
            int slot = tid + i * 256;
            int m  = slot >> 3;
            int kq = (slot & 7) * 4;
            float4 v = *(const float4*)(Ub + (size_t)(l0 + m) * DD + k0 + kq);
            As[kq + 0][m] = bsplit(v.x);
            As[kq + 1][m] = bsplit(v.y);
            As[kq + 2][m] = bsplit(v.z);
            As[kq + 3][m] = bsplit(v.w);
            int nq = (slot & 31) * 4;
            int kk = slot >> 5;
            float4 w4 = *(const float4*)(W + (size_t)(k0 + kk) * INNER + c0 + nq);
            uint4 pw = make_uint4(bsplit(w4.x), bsplit(w4.y), bsplit(w4.z), bsplit(w4.w));
            *(uint4*)&Bs[kk][nq] = pw;
        }
        __syncthreads();

        #pragma unroll
        for (int s = 0; s < 2; s++) {
            const int kb = 16 * s;
            uint32_t bh[4][2], bl[4][2];
            #pragma unroll
            for (int nt = 0; nt < 4; nt++) {
                int n = warp_n * 32 + nt * 8 + q;
                uint32_t p0 = Bs[kb + 2 * r][n],     p1 = Bs[kb + 2 * r + 1][n];
                uint32_t q0 = Bs[kb + 8 + 2 * r][n], q1 = Bs[kb + 9 + 2 * r][n];
                bh[nt][0] = PHI(p0, p1); bl[nt][0] = PLO(p0, p1);
                bh[nt][1] = PHI(q0, q1); bl[nt][1] = PLO(q0, q1);
            }
            #pragma unroll
            for (int mt = 0; mt < 4; mt++) {
                int m = warp_m * 64 + mt * 16 + q;
                uint32_t p00 = As[kb + 2 * r][m],         p01 = As[kb + 2 * r + 1][m];
                uint32_t p10 = As[kb + 2 * r][m + 8],     p11 = As[kb + 2 * r + 1][m + 8];
                uint32_t p20 = As[kb + 8 + 2 * r][m],     p21 = As[kb + 9 + 2 * r][m];
                uint32_t p30 = As[kb + 8 + 2 * r][m + 8], p31 = As[kb + 9 + 2 * r][m + 8];
                uint32_t ah[4], al[4];
                ah[0] = PHI(p00, p01); al[0] = PLO(p00, p01);
                ah[1] = PHI(p10, p11); al[1] = PLO(p10, p11);
                ah[2] = PHI(p20, p21); al[2] = PLO(p20, p21);
                ah[3] = PHI(p30, p31); al[3] = PLO(p30, p31);
                #pragma unroll
                for (int nt = 0; nt < 4; nt++) {
                    mma_bf16(acc[mt][nt], ah, bh[nt]);
                    mma_bf16(acc[mt][nt], ah, bl[nt]);
                    mma_bf16(acc[mt][nt], al, bh[nt]);
                }
            }
        }
        __syncthreads();
    }

    // epilogue: transpose through smem, store [c][l] rows contiguous
    float* st = (float*)&As[0][0];   // 32 x 129 floats scratch (fits in 32x132)
    for (int p = 0; p < 4; p++) {
        if (warp_n == p) {
            #pragma unroll
            for (int mt = 0; mt < 4; mt++)
                #pragma unroll
                for (int nt = 0; nt < 4; nt++) {
                    int m = warp_m * 64 + mt * 16 + q;
                    int n = nt * 8 + 2 * r;
                    st[(n    ) * 129 + m    ] = acc[mt][nt][0];
                    st[(n + 1) * 129 + m    ] = acc[mt][nt][1];
                    st[(n    ) * 129 + m + 8] = acc[mt][nt][2];
                    st[(n + 1) * 129 + m + 8] = acc[mt][nt][3];
                }
        }
        __syncthreads();
        int row = tid >> 3;
        int cq  = tid & 7;
        int c   = c0 + p * 32 + row;
        float bb = bias[c];
        float* dst = Cb + (size_t)c * LL + l0;
        #pragma unroll
        for (int ii = 0; ii < 4; ii++) {
            int mq = cq + 8 * ii;
            float4 v = make_float4(st[row * 129 + mq * 4 + 0] + bb,
                                   st[row * 129 + mq * 4 + 1] + bb,
                                   st[row * 129 + mq * 4 + 2] + bb,
                                   st[row * 129 + mq * 4 + 3] + bb);
            *(float4*)(dst + mq * 4) = v;
        }
        __syncthreads();
    }
}

// ---------------- kernel 4: fused FFT conv (register radix-4, bias pre-folded) ----
__global__ __launch_bounds__(FNTH) void fftconv_kernel(
    const float* __restrict__ sw, const float* __restrict__ sb)
{
    extern __shared__ float2 smem_f2[];
    float2* sm = smem_f2;
    float2* tw = smem_f2 + DATA_PAD;
    const int pr  = blockIdx.x;
    const int b   = blockIdx.y;
    const int tid = threadIdx.x;
    const int f0  = 2 * pr;
    const int f1  = 2 * pr + 1;

    build_twiddles4(tw, tid);

    float2 e[16];
    {
        const float* r0 = d_proj + ((size_t)b * INNER + f0) * LL;
        const float* r1 = d_proj + ((size_t)b * INNER + f1) * LL;
        float a0 = sw[f0], a1 = sw[INNER + f0], a2 = sw[2 * INNER + f0], ab = sb[f0];
        float c0 = sw[f1], c1 = sw[INNER + f1], c2 = sw[2 * INNER + f1], cb = sb[f1];
        #pragma unroll
        for (int i = 0; i < 8; i++) {
            int l = tid + 1024 * i;
            e[i] = make_float2(scval(r0, l, a0, a1, a2, ab),
                               scval(r1, l, c0, c1, c2, cb));
        }
        #pragma unroll
        for (int i = 8; i < 16; i++) e[i] = make_float2(0.0f, 0.0f);
    }
    __syncthreads();

    #pragma unroll 1
    for (int o = 0; o < ORDER; o++) {
        fft16k_fwd_regs<true>(sm, tw, e, tid);

        const float2* hf0 = d_hf + (size_t)((o * NPAIR + pr) * 2 + 0) * N2;
        const float2* hf1 = d_hf + (size_t)((o * NPAIR + pr) * 2 + 1) * N2;
        #pragma unroll
        for (int i = 0; i < 16; i++) {
            int p  = tid + 1024 * i;
            int k  = dr4(p);
            int km = (N2 - k) & (N2 - 1);
            int pm = dr4(km);
            if (p <= pm) {
                float2 z1 = sm[PD(p)];
                float2 z2 = sm[PD(pm)];
                float2 V0 = make_float2(0.5f * (z1.x + z2.x),  0.5f * (z1.y - z2.y));
                float2 V1 = make_float2(0.5f * (z1.y + z2.y), -0.5f * (z1.x - z2.x));
                float2 Y0 = cmul(V0, hf0[p]);
                float2 Y1 = cmul(V1, hf1[p]);
                sm[PD(p)]  = make_float2(Y0.x - Y1.y, Y0.y + Y1.x);
                sm[PD(pm)] = make_float2(Y0.x + Y1.y, Y1.x - Y0.y);
            }
        }
        __syncthreads();

        fft16k_inv_regs(sm, tw, e, tid);

        {
            const int g0c = (1 + o) * FF + f0;
            const int g1c = (1 + o) * FF + f1;
            const float* g0r = d_proj + ((size_t)b * INNER + g0c) * LL;
            const float* g1r = d_proj + ((size_t)b * INNER + g1c) * LL;
            float ga0 = sw[g0c], ga1 = sw[INNER + g0c], ga2 = sw[2 * INNER + g0c], gab = sb[g0c];
            float gc0 = sw[g1c], gc1 = sw[INNER + g1c], gc2 = sw[2 * INNER + g1c], gcb = sb[g1c];
            #pragma unroll
            for (int i = 0; i < 8; i++) {
                int l = tid + 1024 * i;
                float g0 = scval(g0r, l, ga0, ga1, ga2, gab);
                float g1 = scval(g1r, l, gc0, gc1, gc2, gcb);
                e[i].x *= g0;
                e[i].y *= g1;
            }
            #pragma unroll
            for (int i = 8; i < 16; i++) e[i] = make_float2(0.0f, 0.0f);
        }
        __syncthreads();
    }

    float* dst0 = d_vout + ((size_t)b * FF + f0) * LL;
    float* dst1 = d_vout + ((size_t)b * FF + f1) * LL;
    #pragma unroll
    for (int i = 0; i < 8; i++) {
        int l = tid + 1024 * i;
        dst0[l] = e[i].x;
        dst1[l] = e[i].y;
    }
}

// ---------------- kernel 5: output GEMM, bf16x3 m16n8k16 ----------------
// Y[b,l,d] = sum_f V[b][f][l]*W[f,d] + bias[d]
__global__ __launch_bounds__(256) void gemm_out_tc(
    const float* __restrict__ W, const float* __restrict__ bias,
    float* __restrict__ Y)
{
    __shared__ uint32_t As[32][132];   // [k(f)][m(l)] packed
    __shared__ uint32_t Bs[32][132];   // [k(f)][n(d)] packed
    const int b  = blockIdx.z;
    const int d0 = blockIdx.x * 128;
    const int l0 = blockIdx.y * 128;
    const float* Vb = d_vout + (size_t)b * FF * LL;
    float* Yb = Y + (size_t)b * LL * DD;

    const int tid    = threadIdx.x;
    const int wid    = tid >> 5;
    const int lane   = tid & 31;
    const int warp_m = wid >> 2;
    const int warp_n = wid & 3;
    const int q      = lane >> 2;
    const int r      = lane & 3;

    float acc[4][4][4];
    #pragma unroll
    for (int mt = 0; mt < 4; mt++)
        #pragma unroll
        for (int nt = 0; nt < 4; nt++)
            #pragma unroll
            for (int j = 0; j < 4; j++) acc[mt][nt][j] = 0.0f;

    for (int k0 = 0; k0 < FF; k0 += 32) {
        #pragma unroll
        for (int i = 0; i < 4; i++) {
            int slot = tid + i * 256;
            int mq = (slot & 31) * 4;
            int kk = slot >> 5;
            float4 v = *(const float4*)(Vb + (size_t)(k0 + kk) * LL + l0 + mq);
            uint4 pv = make_uint4(bsplit(v.x), bsplit(v.y), bsplit(v.z), bsplit(v.w));
            *(uint4*)&As[kk][mq] = pv;
            float4 w4 = *(const float4*)(W + (size_t)(k0 + kk) * DD + d0 + mq);
            uint4 pw = make_uint4(bsplit(w4.x), bsplit(w4.y), bsplit(w4.z), bsplit(w4.w));
            *(uint4*)&Bs[kk][mq] = pw;
        }
        __syncthreads();

        #pragma unroll
        for (int s = 0; s < 2; s++) {
            const int kb = 16 * s;
            uint32_t bh[4][2], bl[4][2];
            #pragma unroll
            for (int nt = 0; nt < 4; nt++) {
                int n = warp_n * 32 + nt * 8 + q;
                uint32_t p0 = Bs[kb + 2 * r][n],     p1 = Bs[kb + 2 * r + 1][n];
                uint32_t q0 = Bs[kb + 8 + 2 * r][n], q1 = Bs[kb + 9 + 2 * r][n];
                bh[nt][0] = PHI(p0, p1); bl[nt][0] = PLO(p0, p1);
                bh[nt][1] = PHI(q0, q1); bl[nt][1] = PLO(q0, q1);
            }
            #pragma unroll
            for (int mt = 0; mt < 4; mt++) {
                int m = warp_m * 64 + mt * 16 + q;
                uint32_t p00 = As[kb + 2 * r][m],         p01 = As[kb + 2 * r + 1][m];
                uint32_t p10 = As[kb + 2 * r][m + 8],     p11 = As[kb + 2 * r + 1][m + 8];
                uint32_t p20 = As[kb + 8 + 2 * r][m],     p21 = As[kb + 9 + 2 * r][m];
                uint32_t p30 = As[kb + 8 + 2 * r][m + 8], p31 = As[kb + 9 + 2 * r][m + 8];
                uint32_t ah[4], al[4];
                ah[0] = PHI(p00, p01); al[0] = PLO(p00, p01);
                ah[1] = PHI(p10, p11); al[1] = PLO(p10, p11);
                ah[2] = PHI(p20, p21); al[2] = PLO(p20, p21);
                ah[3] = PHI(p30, p31); al[3] = PLO(p30, p31);
                #pragma unroll
                for (int nt = 0; nt < 4; nt++) {
                    mma_bf16(acc[mt][nt], ah, bh[nt]);
                    mma_bf16(acc[mt][nt], ah, bl[nt]);
                    mma_bf16(acc[mt][nt], al, bh[nt]);
                }
            }
        }
        __syncthreads();
    }

    #pragma unroll
    for (int mt = 0; mt < 4; mt++) {
        #pragma unroll
        for (int nt = 0; nt < 4; nt++) {
            int n = d0 + warp_n * 32 + nt * 8 + 2 * r;
            float b0v = bias[n], b1v = bias[n + 1];
            int m = l0 + warp_m * 64 + mt * 16 + q;
            float2 o0 = make_float2(acc[mt][nt][0] + b0v, acc[mt][nt][1] + b1v);
            float2 o1 = make_float2(acc[mt][nt][2] + b0v, acc[mt][nt][3] + b1v);
            *(float2*)(Yb + (size_t)m * DD + n)       = o0;
            *(float2*)(Yb + (size_t)(m + 8) * DD + n) = o1;
        }
    }
}

// ---------------- launch ----------------
extern "C" void kernel_launch(void* const* d_in, const int* in_sizes, int n_in,
                              void* d_out, int out_size) {
    const float* u     = (const float*)d_in[0];
    const float* fw1   = (const float*)d_in[1];
    const float* fb1   = (const float*)d_in[2];
    const float* fw2   = (const float*)d_in[3];
    const float* fb2   = (const float*)d_in[4];
    const float* decay = (const float*)d_in[5];
    const float* bias  = (const float*)d_in[6];
    const float* ipw   = (const float*)d_in[7];
    const float* ipb   = (const float*)d_in[8];
    const float* sw    = (const float*)d_in[9];
    const float* sb    = (const float*)d_in[10];
    const float* ow    = (const float*)d_in[11];
    const float* ob    = (const float*)d_in[12];
    float* y = (float*)d_out;

    cudaFuncSetAttribute(hfft_kernel,    cudaFuncAttributeMaxDynamicSharedMemorySize, SMEM_FFT);
    cudaFuncSetAttribute(fftconv_kernel, cudaFuncAttributeMaxDynamicSharedMemorySize, SMEM_FFT);

    hfilter_kernel<<<N2 / 16, 256>>>(fw1, fb1, fw2, fb2, decay);
    hfft_kernel<<<ORDER * NPAIR, FNTH, SMEM_FFT>>>(bias);
    gemm_inproj_tc<<<dim3(INNER / 128, LL / 128, BB), 256>>>(u, ipw, ipb);
    fftconv_kernel<<<dim3(NPAIR, BB), FNTH, SMEM_FFT>>>(sw, sb);
    gemm_out_tc<<<dim3(DD / 128, LL / 128, BB), 256>>>(ow, ob, y);
}

// round 12
// speedup vs baseline: 1.6468x; 1.0356x over previous
#include <cuda_runtime.h>
#include <cuda_bf16.h>
#include <math.h>
#include <stdint.h>

// ---------------- problem constants ----------------
#define BB    2
#define LL    8192
#define N2    16384      // 2*L, FFT length = 4^7
#define DD    768
#define FF    768
#define ORDER 2
#define INNER 2304       // F*(ORDER+1)
#define NPAIR 384        // FF/2 channel pairs
#define FNTH  1024       // threads for FFT kernels

// padded smem layout for FFT data: +2 float2 per 64 elements
#define PD(i) ((i) + 2 * ((i) >> 6))
#define DATA_PAD 16896
#define SMEM_FFT ((DATA_PAD + N2 / 4) * 8)   // 167936 B

// GEMM: double-buffered packed tiles, [k][idx] stride 132
#define GSTRIDE 132
#define GTILE   (32 * GSTRIDE)               // one As or Bs tile (uint32)
#define SMEM_GEMM (4 * GTILE * 4)            // 2 buffers x (As+Bs) = 67584 B

// ---------------- scratch (static device memory; no allocation) ----------------
__device__ float2 d_h2 [(size_t)ORDER * NPAIR * N2];
__device__ float2 d_hf [(size_t)ORDER * NPAIR * 2 * N2];    // (fft(h)+bias)/n, dr4 order
__device__ float  d_proj[(size_t)BB * INNER * LL];
__device__ float  d_vout[(size_t)BB * FF * LL];

// ---------------- complex helpers ----------------
__device__ __forceinline__ float2 cadd(float2 a, float2 b) { return make_float2(a.x + b.x, a.y + b.y); }
__device__ __forceinline__ float2 csub(float2 a, float2 b) { return make_float2(a.x - b.x, a.y - b.y); }
__device__ __forceinline__ float2 cmul(float2 a, float2 b) {
    return make_float2(a.x * b.x - a.y * b.y, a.x * b.y + a.y * b.x);
}
__device__ __forceinline__ float2 cmulc(float2 a, float2 b) {
    return make_float2(a.x * b.x + a.y * b.y, a.y * b.x - a.x * b.y);
}

__device__ __forceinline__ int dr4(int p) {
    unsigned r = __brev((unsigned)p) >> 18;
    return (int)(((r & 0x2AAAu) >> 1) | ((r & 0x1555u) << 1));
}

// ---------------- radix-4 butterflies ----------------
__device__ __forceinline__ void bf4_fwd(float2& a, float2& b, float2& c, float2& d, float2 w1) {
    float2 w2 = cmul(w1, w1), w3 = cmul(w2, w1);
    float2 t0 = cadd(a, c), t1 = csub(a, c), t2 = cadd(b, d), t3 = csub(b, d);
    a = cadd(t0, t2);
    float2 X1 = make_float2(t1.x + t3.y, t1.y - t3.x);
    float2 X2 = csub(t0, t2);
    float2 X3 = make_float2(t1.x - t3.y, t1.y + t3.x);
    b = cmul(X1, w1); c = cmul(X2, w2); d = cmul(X3, w3);
}
__device__ __forceinline__ void bf4_fwd_nw(float2& a, float2& b, float2& c, float2& d) {
    float2 t0 = cadd(a, c), t1 = csub(a, c), t2 = cadd(b, d), t3 = csub(b, d);
    a = cadd(t0, t2);
    float2 X1 = make_float2(t1.x + t3.y, t1.y - t3.x);
    float2 X2 = csub(t0, t2);
    float2 X3 = make_float2(t1.x - t3.y, t1.y + t3.x);
    b = X1; c = X2; d = X3;
}
__device__ __forceinline__ void bf4_inv(float2& a, float2& b, float2& c, float2& d, float2 w1) {
    float2 w2 = cmul(w1, w1), w3 = cmul(w2, w1);
    float2 b1 = cmulc(b, w1), b2 = cmulc(c, w2), b3 = cmulc(d, w3);
    float2 s0 = cadd(a, b2), s1 = csub(a, b2), s2 = cadd(b1, b3), s3 = csub(b1, b3);
    a = cadd(s0, s2);
    b = make_float2(s1.x - s3.y, s1.y + s3.x);
    c = csub(s0, s2);
    d = make_float2(s1.x + s3.y, s1.y - s3.x);
}
__device__ __forceinline__ void bf4_inv_nw(float2& a, float2& b, float2& c, float2& d) {
    float2 s0 = cadd(a, c), s1 = csub(a, c), s2 = cadd(b, d), s3 = csub(b, d);
    a = cadd(s0, s2);
    b = make_float2(s1.x - s3.y, s1.y + s3.x);
    c = csub(s0, s2);
    d = make_float2(s1.x + s3.y, s1.y - s3.x);
}

__device__ __forceinline__ void build_twiddles4(float2* tw4, int tid) {
    #pragma unroll
    for (int i = 0; i < N2 / 4 / FNTH; i++) {
        int j = tid + i * FNTH;
        float x = -(float)j * (1.0f / 8192.0f);
        float s, c;
        sincospif(x, &s, &c);
        tw4[j] = make_float2(c, s);
    }
}

// ---------------- register-resident 16K FFT (round-8, unchanged) ----------------
template <bool ZPAD>
__device__ __forceinline__ void fft16k_fwd_regs(float2* sm, const float2* tw, float2 e[16], int tid) {
    #pragma unroll
    for (int r0 = 0; r0 < 4; r0++) {
        float2 w1 = tw[tid + 1024 * r0];
        if (ZPAD) {
            float2 a = e[r0], b = e[r0 + 4];
            float2 w2 = cmul(w1, w1), w3 = cmul(w2, w1);
            e[r0]      = cadd(a, b);
            e[r0 + 4]  = cmul(make_float2(a.x + b.y, a.y - b.x), w1);
            e[r0 + 8]  = cmul(csub(a, b), w2);
            e[r0 + 12] = cmul(make_float2(a.x - b.y, a.y + b.x), w3);
        } else {
            bf4_fwd(e[r0], e[r0 + 4], e[r0 + 8], e[r0 + 12], w1);
        }
    }
    {
        float2 w1 = tw[tid << 2];
        #pragma unroll
        for (int g = 0; g < 4; g++) bf4_fwd(e[4 * g], e[4 * g + 1], e[4 * g + 2], e[4 * g + 3], w1);
    }
    #pragma unroll
    for (int r = 0; r < 16; r++) sm[PD(tid + 1024 * r)] = e[r];
    __syncthreads();

    {
        const int off  = tid & 63;
        const int base = ((tid >> 6) << 10) + off;
        #pragma unroll
        for (int r = 0; r < 16; r++) e[r] = sm[PD(base + 64 * r)];
        #pragma unroll
        for (int r0 = 0; r0 < 4; r0++)
            bf4_fwd(e[r0], e[r0 + 4], e[r0 + 8], e[r0 + 12], tw[(off + 64 * r0) << 4]);
        float2 w1 = tw[off << 6];
        #pragma unroll
        for (int g = 0; g < 4; g++) bf4_fwd(e[4 * g], e[4 * g + 1], e[4 * g + 2], e[4 * g + 3], w1);
        #pragma unroll
        for (int r = 0; r < 16; r++) sm[PD(base + 64 * r)] = e[r];
    }
    __syncthreads();

    {
        const int c4   = tid & 3;
        const int base = ((tid >> 2) << 6) + c4;
        #pragma unroll
        for (int r = 0; r < 16; r++) e[r] = sm[PD(base + 4 * r)];
        #pragma unroll
        for (int r0 = 0; r0 < 4; r0++)
            bf4_fwd(e[r0], e[r0 + 4], e[r0 + 8], e[r0 + 12], tw[(4 * r0 + c4) << 8]);
        float2 w1 = tw[c4 << 10];
        #pragma unroll
        for (int g = 0; g < 4; g++) bf4_fwd(e[4 * g], e[4 * g + 1], e[4 * g + 2], e[4 * g + 3], w1);
        #pragma unroll
        for (int r = 0; r < 16; r++) sm[PD(base + 4 * r)] = e[r];
    }
    __syncthreads();

    #pragma unroll
    for (int k = 0; k < 4; k++) {
        int si = PD(4 * (tid + 1024 * k));
        float4 lo = *(float4*)&sm[si];
        float4 hi = *(float4*)&sm[si + 2];
        float2 a = make_float2(lo.x, lo.y), b = make_float2(lo.z, lo.w);
        float2 c = make_float2(hi.x, hi.y), d = make_float2(hi.z, hi.w);
        bf4_fwd_nw(a, b, c, d);
        *(float4*)&sm[si]     = make_float4(a.x, a.y, b.x, b.y);
        *(float4*)&sm[si + 2] = make_float4(c.x, c.y, d.x, d.y);
    }
    __syncthreads();
}

__device__ __forceinline__ void fft16k_inv_regs(float2* sm, const float2* tw, float2 e[16], int tid) {
    #pragma unroll
    for (int k = 0; k < 4; k++) {
        int si = PD(4 * (tid + 1024 * k));
        float4 lo = *(float4*)&sm[si];
        float4 hi = *(float4*)&sm[si + 2];
        float2 a = make_float2(lo.x, lo.y), b = make_float2(lo.z, lo.w);
        float2 c = make_float2(hi.x, hi.y), d = make_float2(hi.z, hi.w);
        bf4_inv_nw(a, b, c, d);
        *(float4*)&sm[si]     = make_float4(a.x, a.y, b.x, b.y);
        *(float4*)&sm[si + 2] = make_float4(c.x, c.y, d.x, d.y);
    }
    __syncthreads();

    {
        const int c4   = tid & 3;
        const int base = ((tid >> 2) << 6) + c4;
        #pragma unroll
        for (int r = 0; r < 16; r++) e[r] = sm[PD(base + 4 * r)];
        float2 w1 = tw[c4 << 10];
        #pragma unroll
        for (int g = 0; g < 4; g++) bf4_inv(e[4 * g], e[4 * g + 1], e[4 * g + 2], e[4 * g + 3], w1);
        #pragma unroll
        for (int r0 = 0; r0 < 4; r0++)
            bf4_inv(e[r0], e[r0 + 4], e[r0 + 8], e[r0 + 12], tw[(4 * r0 + c4) << 8]);
        #pragma unroll
        for (int r = 0; r < 16; r++) sm[PD(base + 4 * r)] = e[r];
    }
    __syncthreads();

    {
        const int off  = tid & 63;
        const int base = ((tid >> 6) << 10) + off;
        #pragma unroll
        for (int r = 0; r < 16; r++) e[r] = sm[PD(base + 64 * r)];
        float2 w1 = tw[off << 6];
        #pragma unroll
        for (int g = 0; g < 4; g++) bf4_inv(e[4 * g], e[4 * g + 1], e[4 * g + 2], e[4 * g + 3], w1);
        #pragma unroll
        for (int r0 = 0; r0 < 4; r0++)
            bf4_inv(e[r0], e[r0 + 4], e[r0 + 8], e[r0 + 12], tw[(off + 64 * r0) << 4]);
        #pragma unroll
        for (int r = 0; r < 16; r++) sm[PD(base + 64 * r)] = e[r];
    }
    __syncthreads();

    #pragma unroll
    for (int r = 0; r < 16; r++) e[r] = sm[PD(tid + 1024 * r)];
    {
        float2 w1 = tw[tid << 2];
        #pragma unroll
        for (int g = 0; g < 4; g++) bf4_inv(e[4 * g], e[4 * g + 1], e[4 * g + 2], e[4 * g + 3], w1);
    }
    #pragma unroll
    for (int r0 = 0; r0 < 4; r0++)
        bf4_inv(e[r0], e[r0 + 4], e[r0 + 8], e[r0 + 12], tw[tid + 1024 * r0]);
}

__device__ __forceinline__ float scval(const float* __restrict__ row, int l,
                                       float w0, float w1, float w2, float bb) {
    float acc = bb + w1 * row[l];
    if (l > 0)      acc += w0 * row[l - 1];
    if (l < LL - 1) acc += w2 * row[l + 1];
    return acc;
}

// ---------------- bf16x3 MMA helpers ----------------
__device__ __forceinline__ uint32_t bsplit(float x) {
    __nv_bfloat16 h = __float2bfloat16_rn(x);
    float fh = __bfloat162float(h);
    __nv_bfloat16 l = __float2bfloat16_rn(x - fh);
    return ((uint32_t)__bfloat16_as_ushort(h) << 16) | (uint32_t)__bfloat16_as_ushort(l);
}
#define PHI(p0, p1) __byte_perm((p0), (p1), 0x7632)
#define PLO(p0, p1) __byte_perm((p0), (p1), 0x5410)

__device__ __forceinline__ void mma_bf16(float* c, const uint32_t* a, const uint32_t* b) {
    asm volatile(
        "mma.sync.aligned.m16n8k16.row.col.f32.bf16.bf16.f32 "
        "{%0,%1,%2,%3}, {%4,%5,%6,%7}, {%8,%9}, {%0,%1,%2,%3};"
        : "+f"(c[0]), "+f"(c[1]), "+f"(c[2]), "+f"(c[3])
        : "r"(a[0]), "r"(a[1]), "r"(a[2]), "r"(a[3]), "r"(b[0]), "r"(b[1]));
}

// shared GEMM compute phase: one 32-k tile from packed As/Bs (stride GSTRIDE)
__device__ __forceinline__ void gemm_tile_compute(
    const uint32_t* As, const uint32_t* Bs, float acc[4][4][4],
    int warp_m, int warp_n, int q, int r)
{
    #pragma unroll
    for (int s = 0; s < 2; s++) {
        const int kb = 16 * s;
        uint32_t bh[4][2], bl[4][2];
        #pragma unroll
        for (int nt = 0; nt < 4; nt++) {
            int n = warp_n * 32 + nt * 8 + q;
            uint32_t p0 = Bs[(kb + 2 * r) * GSTRIDE + n],     p1 = Bs[(kb + 2 * r + 1) * GSTRIDE + n];
            uint32_t q0 = Bs[(kb + 8 + 2 * r) * GSTRIDE + n], q1 = Bs[(kb + 9 + 2 * r) * GSTRIDE + n];
            bh[nt][0] = PHI(p0, p1); bl[nt][0] = PLO(p0, p1);
            bh[nt][1] = PHI(q0, q1); bl[nt][1] = PLO(q0, q1);
        }
        #pragma unroll
        for (int mt = 0; mt < 4; mt++) {
            int m = warp_m * 64 + mt * 16 + q;
            uint32_t p00 = As[(kb + 2 * r) * GSTRIDE + m],         p01 = As[(kb + 2 * r + 1) * GSTRIDE + m];
            uint32_t p10 = As[(kb + 2 * r) * GSTRIDE + m + 8],     p11 = As[(kb + 2 * r + 1) * GSTRIDE + m + 8];
            uint32_t p20 = As[(kb + 8 + 2 * r) * GSTRIDE + m],     p21 = As[(kb + 9 + 2 * r) * GSTRIDE + m];
            uint32_t p30 = As[(kb + 8 + 2 * r) * GSTRIDE + m + 8], p31 = As[(kb + 9 + 2 * r) * GSTRIDE + m + 8];
            uint32_t ah[4], al[4];
            ah[0] = PHI(p00, p01); al[0] = PLO(p00, p01);
            ah[1] = PHI(p10, p11); al[1] = PLO(p10, p11);
            ah[2] = PHI(p20, p21); al[2] = PLO(p20, p21);
            ah[3] = PHI(p30, p31); al[3] = PLO(p30, p31);
            #pragma unroll
            for (int nt = 0; nt < 4; nt++) {
                mma_bf16(acc[mt][nt], ah, bh[nt]);
                mma_bf16(acc[mt][nt], ah, bl[nt]);
                mma_bf16(acc[mt][nt], al, bh[nt]);
            }
        }
    }
}

// ---------------- kernel 1: filter MLP + modulation ----------------
__global__ __launch_bounds__(256) void hfilter_kernel(
    const float* __restrict__ w1, const float* __restrict__ b1,
    const float* __restrict__ w2, const float* __restrict__ b2,
    const float* __restrict__ decay)
{
    __shared__ float hid[16][64];
    const int p0  = blockIdx.x * 16;
    const int tid = threadIdx.x;

    for (int idx = tid; idx < 16 * 64; idx += 256) {
        int pp = idx >> 6;
        int u  = idx & 63;
        int p  = p0 + pp;
        float off = (p < LL) ? (float)p : (float)(p - N2);
        float t[9];
        t[0] = off * (1.0f / 8192.0f);
        const float step = (8192.0f - 4.0f) / 3.0f;
        #pragma unroll
        for (int i = 0; i < 4; i++) {
            float period = 4.0f + step * (float)i;
            float fr = 6.28318530717958647692f / period;
            float ph = off * fr;
            t[1 + i] = cosf(ph);
            t[5 + i] = sinf(ph);
        }
        float a = b1[u];
        #pragma unroll
        for (int k = 0; k < 9; k++) a += t[k] * w1[k * 64 + u];
        hid[pp][u] = sinf(a);
    }
    __syncthreads();

    for (int oc = tid; oc < ORDER * FF; oc += 256) {
        float acc[16];
        float bv = b2[oc];
        #pragma unroll
        for (int pp = 0; pp < 16; pp++) acc[pp] = bv;
        for (int k = 0; k < 64; k++) {
            float wv = w2[k * (ORDER * FF) + oc];
            #pragma unroll
            for (int pp = 0; pp < 16; pp++) acc[pp] += hid[pp][k] * wv;
        }
        float dec = fabsf(decay[oc]);
        int o = oc / FF, f = oc - o * FF;
        float* dst = (float*)(d_h2 + ((size_t)(o * NPAIR + (f >> 1))) * N2 + p0) + (f & 1);
        #pragma unroll
        for (int pp = 0; pp < 16; pp++) {
            int p = p0 + pp;
            float mod = (p < LL) ? (float)p * (1.0f / 8191.0f)
                                 : (float)(N2 - 1 - p) * (1.0f / 8191.0f);
            dst[2 * pp] = acc[pp] * expf(-mod * dec);
        }
    }
}

// ---------------- kernel 2: paired filter FFT (register radix-4, bias folded) ----
__global__ __launch_bounds__(FNTH) void hfft_kernel(const float* __restrict__ bias) {
    extern __shared__ float2 smem_f2[];
    float2* sm = smem_f2;
    float2* tw = smem_f2 + DATA_PAD;
    const int cp  = blockIdx.x;
    const int tid = threadIdx.x;

    build_twiddles4(tw, tid);
    float2 e[16];
    const float2* src = d_h2 + (size_t)cp * N2;
    #pragma unroll
    for (int r = 0; r < 16; r++) e[r] = src[tid + 1024 * r];
    __syncthreads();

    fft16k_fwd_regs<false>(sm, tw, e, tid);

    const int o  = cp / NPAIR;
    const int f0 = 2 * (cp % NPAIR);
    const float c0 = bias[o * FF + f0]     * (1.0f / (float)N2);
    const float c1 = bias[o * FF + f0 + 1] * (1.0f / (float)N2);
    const float s  = 0.5f / (float)N2;
    float2* hf0 = d_hf + (size_t)(cp * 2 + 0) * N2;
    float2* hf1 = d_hf + (size_t)(cp * 2 + 1) * N2;
    #pragma unroll
    for (int i = 0; i < 16; i++) {
        int p  = tid + 1024 * i;
        int k  = dr4(p);
        int km = (N2 - k) & (N2 - 1);
        int pm = dr4(km);
        if (p <= pm) {
            float2 z1 = sm[PD(p)];
            float2 z2 = sm[PD(pm)];
            float2 H0 = make_float2(s * (z1.x + z2.x) + c0,  s * (z1.y - z2.y));
            float2 H1 = make_float2(s * (z1.y + z2.y) + c1, -s * (z1.x - z2.x));
            hf0[p]  = H0;
            hf1[p]  = H1;
            hf0[pm] = make_float2(H0.x, -H0.y);
            hf1[pm] = make_float2(H1.x, -H1.y);
        }
    }
}

// ---------------- kernel 3: in-projection GEMM, bf16x3, double-buffered pipeline ---
// C[b,c,l] = sum_d U[b,l,d]*W[d,c] + bias[c]  (output transposed [c][l])
__global__ __launch_bounds__(256, 2) void gemm_inproj_tc(
    const float* __restrict__ U, const float* __restrict__ W,
    const float* __restrict__ bias)
{
    extern __shared__ uint32_t gsm[];
    const int b  = blockIdx.z;
    const int c0 = blockIdx.x * 128;
    const int l0 = blockIdx.y * 128;
    const float* Ub = U + (size_t)b * LL * DD;
    float* Cb = d_proj + (size_t)b * INNER * LL;

    const int tid    = threadIdx.x;
    const int wid    = tid >> 5;
    const int lane   = tid & 31;
    const int warp_m = wid >> 2;
    const int warp_n = wid & 3;
    const int q      = lane >> 2;
    const int r      = lane & 3;

    // loader indices (fixed per thread)
    const int am  = tid >> 1;                 // slot pattern: i in 0..3, slot=tid+256i
    const int akq = (tid & 1) << 2;           //   -> m = slot>>3 covers via 4 iters below

    float acc[4][4][4];
    #pragma unroll
    for (int mt = 0; mt < 4; mt++)
        #pragma unroll
        for (int nt = 0; nt < 4; nt++)
            #pragma unroll
            for (int j = 0; j < 4; j++) acc[mt][nt][j] = 0.0f;

    float4 va[4], vb[4];
    // prologue: load tile 0
    #pragma unroll
    for (int i = 0; i < 4; i++) {
        int slot = tid + i * 256;
        int m  = slot >> 3;
        int kq = (slot & 7) * 4;
        va[i] = *(const float4*)(Ub + (size_t)(l0 + m) * DD + kq);
        int nq = (slot & 31) * 4;
        int kk = slot >> 5;
        vb[i] = *(const float4*)(W + (size_t)kk * INNER + c0 + nq);
    }
    {   // convert + store tile 0 to buffer 0
        uint32_t* As = gsm;
        uint32_t* Bs = gsm + GTILE;
        #pragma unroll
        for (int i = 0; i < 4; i++) {
            int slot = tid + i * 256;
            int m  = slot >> 3;
            int kq = (slot & 7) * 4;
            As[(kq + 0) * GSTRIDE + m] = bsplit(va[i].x);
            As[(kq + 1) * GSTRIDE + m] = bsplit(va[i].y);
            As[(kq + 2) * GSTRIDE + m] = bsplit(va[i].z);
            As[(kq + 3) * GSTRIDE + m] = bsplit(va[i].w);
            int nq = (slot & 31) * 4;
            int kk = slot >> 5;
            uint4 pw = make_uint4(bsplit(vb[i].x), bsplit(vb[i].y), bsplit(vb[i].z), bsplit(vb[i].w));
            *(uint4*)&Bs[kk * GSTRIDE + nq] = pw;
        }
    }
    __syncthreads();

    const int T = DD / 32;   // 24 tiles
    for (int t = 0; t < T; t++) {
        if (t + 1 < T) {
            int k0n = (t + 1) * 32;
            #pragma unroll
            for (int i = 0; i < 4; i++) {
                int slot = tid + i * 256;
                int m  = slot >> 3;
                int kq = (slot & 7) * 4;
                va[i] = *(const float4*)(Ub + (size_t)(l0 + m) * DD + k0n + kq);
                int nq = (slot & 31) * 4;
                int kk = slot >> 5;
                vb[i] = *(const float4*)(W + (size_t)(k0n + kk) * INNER + c0 + nq);
            }
        }
        const uint32_t* Asr = gsm + (t & 1) * 2 * GTILE;
        const uint32_t* Bsr = Asr + GTILE;
        gemm_tile_compute(Asr, Bsr, acc, warp_m, warp_n, q, r);
        if (t + 1 < T) {
            uint32_t* As = gsm + ((t + 1) & 1) * 2 * GTILE;
            uint32_t* Bs = As + GTILE;
            #pragma unroll
            for (int i = 0; i < 4; i++) {
                int slot = tid + i * 256;
                int m  = slot >> 3;
                int kq = (slot & 7) * 4;
                As[(kq + 0) * GSTRIDE + m] = bsplit(va[i].x);
                As[(kq + 1) * GSTRIDE + m] = bsplit(va[i].y);
                As[(kq + 2) * GSTRIDE + m] = bsplit(va[i].z);
                As[(kq + 3) * GSTRIDE + m] = bsplit(va[i].w);
                int nq = (slot & 31) * 4;
                int kk = slot >> 5;
                uint4 pw = make_uint4(bsplit(vb[i].x), bsplit(vb[i].y), bsplit(vb[i].z), bsplit(vb[i].w));
                *(uint4*)&Bs[kk * GSTRIDE + nq] = pw;
            }
        }
        __syncthreads();
    }

    // epilogue: transpose through smem, store [c][l] rows contiguous
    float* st = (float*)gsm;   // 32 x 129 floats scratch
    for (int p = 0; p < 4; p++) {
        if (warp_n == p) {
            #pragma unroll
            for (int mt = 0; mt < 4; mt++)
                #pragma unroll
                for (int nt = 0; nt < 4; nt++) {
                    int m = warp_m * 64 + mt * 16 + q;
                    int n = nt * 8 + 2 * r;
                    st[(n    ) * 129 + m    ] = acc[mt][nt][0];
                    st[(n + 1) * 129 + m    ] = acc[mt][nt][1];
                    st[(n    ) * 129 + m + 8] = acc[mt][nt][2];
                    st[(n + 1) * 129 + m + 8] = acc[mt][nt][3];
                }
        }
        __syncthreads();
        int row = tid >> 3;
        int cq  = tid & 7;
        int c   = c0 + p * 32 + row;
        float bb = bias[c];
        float* dst = Cb + (size_t)c * LL + l0;
        #pragma unroll
        for (int ii = 0; ii < 4; ii++) {
            int mq = cq + 8 * ii;
            float4 v = make_float4(st[row * 129 + mq * 4 + 0] + bb,
                                   st[row * 129 + mq * 4 + 1] + bb,
                                   st[row * 129 + mq * 4 + 2] + bb,
                                   st[row * 129 + mq * 4 + 3] + bb);
            *(float4*)(dst + mq * 4) = v;
        }
        __syncthreads();
    }
}

// ---------------- kernel 4: fused FFT conv (register radix-4, bias pre-folded) ----
__global__ __launch_bounds__(FNTH) void fftconv_kernel(
    const float* __restrict__ sw, const float* __restrict__ sb)
{
    extern __shared__ float2 smem_f2[];
    float2* sm = smem_f2;
    float2* tw = smem_f2 + DATA_PAD;
    const int pr  = blockIdx.x;
    const int b   = blockIdx.y;
    const int tid = threadIdx.x;
    const int f0  = 2 * pr;
    const int f1  = 2 * pr + 1;

    build_twiddles4(tw, tid);

    float2 e[16];
    {
        const float* r0 = d_proj + ((size_t)b * INNER + f0) * LL;
        const float* r1 = d_proj + ((size_t)b * INNER + f1) * LL;
        float a0 = sw[f0], a1 = sw[INNER + f0], a2 = sw[2 * INNER + f0], ab = sb[f0];
        float c0 = sw[f1], c1 = sw[INNER + f1], c2 = sw[2 * INNER + f1], cb = sb[f1];
        #pragma unroll
        for (int i = 0; i < 8; i++) {
            int l = tid + 1024 * i;
            e[i] = make_float2(scval(r0, l, a0, a1, a2, ab),
                               scval(r1, l, c0, c1, c2, cb));
        }
        #pragma unroll
        for (int i = 8; i < 16; i++) e[i] = make_float2(0.0f, 0.0f);
    }
    __syncthreads();

    #pragma unroll 1
    for (int o = 0; o < ORDER; o++) {
        fft16k_fwd_regs<true>(sm, tw, e, tid);

        const float2* hf0 = d_hf + (size_t)((o * NPAIR + pr) * 2 + 0) * N2;
        const float2* hf1 = d_hf + (size_t)((o * NPAIR + pr) * 2 + 1) * N2;
        #pragma unroll
        for (int i = 0; i < 16; i++) {
            int p  = tid + 1024 * i;
            int k  = dr4(p);
            int km = (N2 - k) & (N2 - 1);
            int pm = dr4(km);
            if (p <= pm) {
                float2 z1 = sm[PD(p)];
                float2 z2 = sm[PD(pm)];
                float2 V0 = make_float2(0.5f * (z1.x + z2.x),  0.5f * (z1.y - z2.y));
                float2 V1 = make_float2(0.5f * (z1.y + z2.y), -0.5f * (z1.x - z2.x));
                float2 Y0 = cmul(V0, hf0[p]);
                float2 Y1 = cmul(V1, hf1[p]);
                sm[PD(p)]  = make_float2(Y0.x - Y1.y, Y0.y + Y1.x);
                sm[PD(pm)] = make_float2(Y0.x + Y1.y, Y1.x - Y0.y);
            }
        }
        __syncthreads();

        fft16k_inv_regs(sm, tw, e, tid);

        {
            const int g0c = (1 + o) * FF + f0;
            const int g1c = (1 + o) * FF + f1;
            const float* g0r = d_proj + ((size_t)b * INNER + g0c) * LL;
            const float* g1r = d_proj + ((size_t)b * INNER + g1c) * LL;
            float ga0 = sw[g0c], ga1 = sw[INNER + g0c], ga2 = sw[2 * INNER + g0c], gab = sb[g0c];
            float gc0 = sw[g1c], gc1 = sw[INNER + g1c], gc2 = sw[2 * INNER + g1c], gcb = sb[g1c];
            #pragma unroll
            for (int i = 0; i < 8; i++) {
                int l = tid + 1024 * i;
                float g0 = scval(g0r, l, ga0, ga1, ga2, gab);
                float g1 = scval(g1r, l, gc0, gc1, gc2, gcb);
                e[i].x *= g0;
                e[i].y *= g1;
            }
            #pragma unroll
            for (int i = 8; i < 16; i++) e[i] = make_float2(0.0f, 0.0f);
        }
        __syncthreads();
    }

    float* dst0 = d_vout + ((size_t)b * FF + f0) * LL;
    float* dst1 = d_vout + ((size_t)b * FF + f1) * LL;
    #pragma unroll
    for (int i = 0; i < 8; i++) {
        int l = tid + 1024 * i;
        dst0[l] = e[i].x;
        dst1[l] = e[i].y;
    }
}

// ---------------- kernel 5: output GEMM, bf16x3, double-buffered pipeline ---------
// Y[b,l,d] = sum_f V[b][f][l]*W[f,d] + bias[d]
__global__ __launch_bounds__(256, 2) void gemm_out_tc(
    const float* __restrict__ W, const float* __restrict__ bias,
    float* __restrict__ Y)
{
    extern __shared__ uint32_t gsm[];
    const int b  = blockIdx.z;
    const int d0 = blockIdx.x * 128;
    const int l0 = blockIdx.y * 128;
    const float* Vb = d_vout + (size_t)b * FF * LL;
    float* Yb = Y + (size_t)b * LL * DD;

    const int tid    = threadIdx.x;
    const int wid    = tid >> 5;
    const int lane   = tid & 31;
    const int warp_m = wid >> 2;
    const int warp_n = wid & 3;
    const int q      = lane >> 2;
    const int r      = lane & 3;

    float acc[4][4][4];
    #pragma unroll
    for (int mt = 0; mt < 4; mt++)
        #pragma unroll
        for (int nt = 0; nt < 4; nt++)
            #pragma unroll
            for (int j = 0; j < 4; j++) acc[mt][nt][j] = 0.0f;

    float4 va[4], vb[4];
    #pragma unroll
    for (int i = 0; i < 4; i++) {
        int slot = tid + i * 256;
        int mq = (slot & 31) * 4;
        int kk = slot >> 5;
        va[i] = *(const float4*)(Vb + (size_t)kk * LL + l0 + mq);
        vb[i] = *(const float4*)(W + (size_t)kk * DD + d0 + mq);
    }
    {
        uint32_t* As = gsm;
        uint32_t* Bs = gsm + GTILE;
        #pragma unroll
        for (int i = 0; i < 4; i++) {
            int slot = tid + i * 256;
            int mq = (slot & 31) * 4;
            int kk = slot >> 5;
            uint4 pv = make_uint4(bsplit(va[i].x), bsplit(va[i].y), bsplit(va[i].z), bsplit(va[i].w));
            *(uint4*)&As[kk * GSTRIDE + mq] = pv;
            uint4 pw = make_uint4(bsplit(vb[i].x), bsplit(vb[i].y), bsplit(vb[i].z), bsplit(vb[i].w));
            *(uint4*)&Bs[kk * GSTRIDE + mq] = pw;
        }
    }
    __syncthreads();

    const int T = FF / 32;   // 24
    for (int t = 0; t < T; t++) {
        if (t + 1 < T) {
            int k0n = (t + 1) * 32;
            #pragma unroll
            for (int i = 0; i < 4; i++) {
                int slot = tid + i * 256;
                int mq = (slot & 31) * 4;
                int kk = slot >> 5;
                va[i] = *(const float4*)(Vb + (size_t)(k0n + kk) * LL + l0 + mq);
                vb[i] = *(const float4*)(W + (size_t)(k0n + kk) * DD + d0 + mq);
            }
        }
        const uint32_t* Asr = gsm + (t & 1) * 2 * GTILE;
        const uint32_t* Bsr = Asr + GTILE;
        gemm_tile_compute(Asr, Bsr, acc, warp_m, warp_n, q, r);
        if (t + 1 < T) {
            uint32_t* As = gsm + ((t + 1) & 1) * 2 * GTILE;
            uint32_t* Bs = As + GTILE;
            #pragma unroll
            for (int i = 0; i < 4; i++) {
                int slot = tid + i * 256;
                int mq = (slot & 31) * 4;
                int kk = slot >> 5;
                uint4 pv = make_uint4(bsplit(va[i].x), bsplit(va[i].y), bsplit(va[i].z), bsplit(va[i].w));
                *(uint4*)&As[kk * GSTRIDE + mq] = pv;
                uint4 pw = make_uint4(bsplit(vb[i].x), bsplit(vb[i].y), bsplit(vb[i].z), bsplit(vb[i].w));
                *(uint4*)&Bs[kk * GSTRIDE + mq] = pw;
            }
        }
        __syncthreads();
    }

    #pragma unroll
    for (int mt = 0; mt < 4; mt++) {
        #pragma unroll
        for (int nt = 0; nt < 4; nt++) {
            int n = d0 + warp_n * 32 + nt * 8 + 2 * r;
            float b0v = bias[n], b1v = bias[n + 1];
            int m = l0 + warp_m * 64 + mt * 16 + q;
            float2 o0 = make_float2(acc[mt][nt][0] + b0v, acc[mt][nt][1] + b1v);
            float2 o1 = make_float2(acc[mt][nt][2] + b0v, acc[mt][nt][3] + b1v);
            *(float2*)(Yb + (size_t)m * DD + n)       = o0;
            *(float2*)(Yb + (size_t)(m + 8) * DD + n) = o1;
        }
    }
}

// ---------------- launch ----------------
extern "C" void kernel_launch(void* const* d_in, const int* in_sizes, int n_in,
                              void* d_out, int out_size) {
    const float* u     = (const float*)d_in[0];
    const float* fw1   = (const float*)d_in[1];
    const float* fb1   = (const float*)d_in[2];
    const float* fw2   = (const float*)d_in[3];
    const float* fb2   = (const float*)d_in[4];
    const float* decay = (const float*)d_in[5];
    const float* bias  = (const float*)d_in[6];
    const float* ipw   = (const float*)d_in[7];
    const float* ipb   = (const float*)d_in[8];
    const float* sw    = (const float*)d_in[9];
    const float* sb    = (const float*)d_in[10];
    const float* ow    = (const float*)d_in[11];
    const float* ob    = (const float*)d_in[12];
    float* y = (float*)d_out;

    cudaFuncSetAttribute(hfft_kernel,    cudaFuncAttributeMaxDynamicSharedMemorySize, SMEM_FFT);
    cudaFuncSetAttribute(fftconv_kernel, cudaFuncAttributeMaxDynamicSharedMemorySize, SMEM_FFT);
    cudaFuncSetAttribute(gemm_inproj_tc, cudaFuncAttributeMaxDynamicSharedMemorySize, SMEM_GEMM);
    cudaFuncSetAttribute(gemm_out_tc,    cudaFuncAttributeMaxDynamicSharedMemorySize, SMEM_GEMM);

    hfilter_kernel<<<N2 / 16, 256>>>(fw1, fb1, fw2, fb2, decay);
    hfft_kernel<<<ORDER * NPAIR, FNTH, SMEM_FFT>>>(bias);
    gemm_inproj_tc<<<dim3(INNER / 128, LL / 128, BB), 256, SMEM_GEMM>>>(u, ipw, ipb);
    fftconv_kernel<<<dim3(NPAIR, BB), FNTH, SMEM_FFT>>>(sw, sb);
    gemm_out_tc<<<dim3(DD / 128, LL / 128, BB), 256, SMEM_GEMM>>>(ow, ob, y);
}